// round 8
// baseline (speedup 1.0000x reference)
#include <cuda_runtime.h>
#include <cuda_fp16.h>
#include <math.h>
#include <stdint.h>

#define D_MODEL 256
#define D_FFN   1024
#define NHEADS  8
#define NLEV    4
#define NPTS    4
#define HDIM    32
#define BATCH   2
#define SLEN    21760
#define NTOK    (BATCH * SLEN)   // 43520

// ================= scratch (device globals; no allocation allowed) =================
__device__ __align__(16) __half g_srcH[NTOK * D_MODEL];
__device__ __align__(16) __half g_qH[NTOK * D_MODEL];
__device__ __align__(16) __half g_sampH[NTOK * D_MODEL];
__device__ __align__(16) __half g_h2H[NTOK * D_MODEL];
__device__ __align__(16) __half g_ffnH[NTOK * D_FFN];
__device__ __align__(16) __half g_valueH[NTOK * D_MODEL];     // planar: [h][tok][dim]

__device__ float g_off[NTOK * D_MODEL];
__device__ float g_attn[NTOK * NHEADS * 16];                  // raw logits
__device__ float g_src2[NTOK * D_MODEL];

// weights transposed [N][K], fp16. w_qa padded to 512 rows (rows 384-511 zero).
__device__ __align__(16) __half w_v[256 * 256];
__device__ __align__(16) __half w_qa[512 * 256];              // 0-255: W_off, 256-383: W_attn, rest 0
__device__ __align__(16) __half w_o[256 * 256];
__device__ __align__(16) __half w_f1[1024 * 256];
__device__ __align__(16) __half w_f2[256 * 1024];

// ================= helpers =================
__device__ __forceinline__ uint32_t smem_u32(const void* p) {
    uint32_t a;
    asm("{ .reg .u64 t; cvta.to.shared.u64 t, %1; cvt.u32.u64 %0, t; }" : "=r"(a) : "l"(p));
    return a;
}
__device__ __forceinline__ void ldm_x4(uint32_t* r, uint32_t addr) {
    asm volatile("ldmatrix.sync.aligned.m8n8.x4.shared.b16 {%0,%1,%2,%3}, [%4];"
                 : "=r"(r[0]), "=r"(r[1]), "=r"(r[2]), "=r"(r[3]) : "r"(addr));
}
__device__ __forceinline__ void mma16816(float* d, const uint32_t* a, const uint32_t* b) {
    asm volatile("mma.sync.aligned.m16n8k16.row.col.f32.f16.f16.f32 "
                 "{%0,%1,%2,%3}, {%4,%5,%6,%7}, {%8,%9}, {%0,%1,%2,%3};"
                 : "+f"(d[0]), "+f"(d[1]), "+f"(d[2]), "+f"(d[3])
                 : "r"(a[0]), "r"(a[1]), "r"(a[2]), "r"(a[3]), "r"(b[0]), "r"(b[1]));
}
__device__ __forceinline__ void cpa16(uint32_t dst, const void* src) {
    asm volatile("cp.async.cg.shared.global [%0], [%1], 16;" :: "r"(dst), "l"(src));
}

// ================= fp16 HMMA GEMM: C[M,N] = epi(A[M,K] @ (B[N,K])^T + bias) =================
// CTA 128(M) x 256(N), 8 warps (2x4) of 64x64, BK=64, 3-stage cp.async ring, 256 threads, 1 CTA/SM.
// EPI: 1 = gelu(x+bias) -> fp16; 2 = x+bias+aux(residual) -> fp32;
//      3 = dual (logical N=384): col<256 -> C(bias), 256<=col<384 -> Cb(aux bias), col>=384 skip;
//      4 = fp16 planar value: Ch[((col>>5)*NTOK+row)*32 + (col&31)]
static const int LDSB  = 144;                    // 64 fp16 (128 B) + 16 B pad
static const int ABUF  = 128 * LDSB;             // 18432 B
static const int BBUF  = 256 * LDSB;             // 36864 B
static const int STAGE = ABUF + BBUF;            // 55296 B
static const int GEMM_SMEM = 3 * STAGE;          // 165888 B

template <int EPI>
__global__ void __launch_bounds__(256, 1) mma_gemm(
    const __half* __restrict__ A, const __half* __restrict__ B,
    const float* __restrict__ bias, const float* __restrict__ aux,
    float* __restrict__ C, float* __restrict__ Cb, __half* __restrict__ Ch,
    int N, int K)
{
    extern __shared__ __align__(16) char sm[];
    const uint32_t smb = smem_u32(sm);
    const int tid = threadIdx.x;
    const int wid = tid >> 5, lane = tid & 31;
    const int wm = wid >> 2, wn = wid & 3;                // 2 x 4 warps of 64x64
    const int m0 = blockIdx.y * 128, n0 = blockIdx.x * 256;
    const int S = K >> 6;

    float acc[4][8][4];
    #pragma unroll
    for (int i = 0; i < 4; i++)
        #pragma unroll
        for (int j = 0; j < 8; j++)
            #pragma unroll
            for (int r = 0; r < 4; r++) acc[i][j][r] = 0.f;

    auto prefetch = [&](int s) {
        int k0 = s << 6;
        const uint32_t ab = smb + (uint32_t)(s % 3) * (uint32_t)STAGE;
        const uint32_t bb = ab + (uint32_t)ABUF;
        #pragma unroll
        for (int i = 0; i < 12; i++) {
            int c = tid + (i << 8);                       // 0..3071
            uint32_t dst; const __half* src;
            if (c < 1024) {                               // A: 128 rows x 8 chunks
                int row = c >> 3, kc = (c & 7) << 3;
                dst = ab + (uint32_t)(row * LDSB + kc * 2);
                src = A + (size_t)(m0 + row) * K + k0 + kc;
            } else {                                      // B: 256 rows x 8 chunks
                int c2 = c - 1024;
                int row = c2 >> 3, kc = (c2 & 7) << 3;
                dst = bb + (uint32_t)(row * LDSB + kc * 2);
                src = B + (size_t)(n0 + row) * K + k0 + kc;
            }
            cpa16(dst, src);
        }
        asm volatile("cp.async.commit_group;");
    };

    prefetch(0);
    if (S > 1) prefetch(1);

    for (int s = 0; s < S; s++) {
        if (s + 1 < S) asm volatile("cp.async.wait_group 1;");
        else           asm volatile("cp.async.wait_group 0;");
        __syncthreads();
        if (s + 2 < S) prefetch(s + 2);

        const uint32_t ab = smb + (uint32_t)(s % 3) * (uint32_t)STAGE;
        const uint32_t bb = ab + (uint32_t)ABUF;
        const uint32_t aoff = ab + (uint32_t)(((lane & 15) + wm * 64) * LDSB + ((lane >> 4) << 4));
        const uint32_t boff = bb + (uint32_t)((((lane & 7) + ((lane >> 4) << 3)) + wn * 64) * LDSB
                                              + (((lane >> 3) & 1) << 4));
        #pragma unroll
        for (int ks = 0; ks < 4; ks++) {
            const uint32_t kb = (uint32_t)(ks << 5);
            uint32_t afr[4][4], bfr[8][2];
            #pragma unroll
            for (int mi = 0; mi < 4; mi++)
                ldm_x4(afr[mi], aoff + (uint32_t)(mi * 16 * LDSB) + kb);
            #pragma unroll
            for (int nj = 0; nj < 4; nj++) {
                uint32_t r[4];
                ldm_x4(r, boff + (uint32_t)(nj * 16 * LDSB) + kb);
                bfr[nj * 2][0] = r[0]; bfr[nj * 2][1] = r[1];
                bfr[nj * 2 + 1][0] = r[2]; bfr[nj * 2 + 1][1] = r[3];
            }
            #pragma unroll
            for (int mi = 0; mi < 4; mi++)
                #pragma unroll
                for (int ni = 0; ni < 8; ni++)
                    mma16816(acc[mi][ni], afr[mi], bfr[ni]);
        }
    }
    __syncthreads();

    // ---- epilogue: stage each warp's 64x64 tile in smem (stride 68 floats), store coalesced ----
    float* ws = (float*)sm + wid * (64 * 68);
    const int er = lane >> 2, ec = (lane & 3) * 2;
    #pragma unroll
    for (int mi = 0; mi < 4; mi++)
        #pragma unroll
        for (int ni = 0; ni < 8; ni++) {
            *(float2*)&ws[(mi * 16 + er) * 68 + ni * 8 + ec]     = make_float2(acc[mi][ni][0], acc[mi][ni][1]);
            *(float2*)&ws[(mi * 16 + er + 8) * 68 + ni * 8 + ec] = make_float2(acc[mi][ni][2], acc[mi][ni][3]);
        }
    __syncwarp();

    const int gcb = n0 + wn * 64 + lane;
    float badd[2];
    #pragma unroll
    for (int cc = 0; cc < 2; cc++) {
        int gc = gcb + cc * 32;
        if (EPI == 3) badd[cc] = (gc < 256) ? bias[gc] : ((gc < 384) ? aux[gc - 256] : 0.f);
        else          badd[cc] = bias[gc];
    }

    for (int r = 0; r < 64; r++) {
        const int gr = m0 + wm * 64 + r;
        #pragma unroll
        for (int cc = 0; cc < 2; cc++) {
            const int gc = gcb + cc * 32;
            float v = ws[r * 68 + cc * 32 + lane] + badd[cc];
            if (EPI == 1) {
                v = 0.5f * v * (1.0f + erff(v * 0.70710678118654752f));
                Ch[(size_t)gr * N + gc] = __float2half(v);
            } else if (EPI == 2) {
                C[(size_t)gr * N + gc] = v + aux[(size_t)gr * N + gc];
            } else if (EPI == 3) {
                if (gc < 256)      C[(size_t)gr * 256 + gc] = v;
                else if (gc < 384) Cb[(size_t)gr * 128 + (gc - 256)] = v;
            } else {  // EPI == 4: planar value
                Ch[((size_t)(gc >> 5) * NTOK + gr) * 32 + (gc & 31)] = __float2half(v);
            }
        }
    }
}

// ================= fused prep: src -> fp16; q = LN1(src)+pos -> fp16 =================
__global__ void pre_kernel(const float* __restrict__ x,
                           const float* __restrict__ gamma,
                           const float* __restrict__ beta,
                           const float* __restrict__ pos) {
    int t = blockIdx.x;
    int c = threadIdx.x;
    float v = x[t * D_MODEL + c];
    g_srcH[(size_t)t * D_MODEL + c] = __float2half(v);
    float a = v, a2 = v * v;
    #pragma unroll
    for (int o = 16; o; o >>= 1) {
        a  += __shfl_xor_sync(0xffffffffu, a,  o);
        a2 += __shfl_xor_sync(0xffffffffu, a2, o);
    }
    __shared__ float s1[8], s2[8];
    if ((c & 31) == 0) { s1[c >> 5] = a; s2[c >> 5] = a2; }
    __syncthreads();
    float sum = 0.f, sq = 0.f;
    #pragma unroll
    for (int i = 0; i < 8; i++) { sum += s1[i]; sq += s2[i]; }
    float mu  = sum * (1.0f / D_MODEL);
    float var = sq * (1.0f / D_MODEL) - mu * mu;
    float rr  = rsqrtf(var + 1e-5f);
    float y   = (v - mu) * rr * gamma[c] + beta[c] + pos[t * D_MODEL + c];
    g_qH[(size_t)t * D_MODEL + c] = __float2half(y);
}

// ================= layernorm2 -> fp16 =================
__global__ void ln2_kernel(const float* __restrict__ x,
                           const float* __restrict__ gamma,
                           const float* __restrict__ beta) {
    int t = blockIdx.x;
    int c = threadIdx.x;
    float v = x[t * D_MODEL + c];
    float a = v, a2 = v * v;
    #pragma unroll
    for (int o = 16; o; o >>= 1) {
        a  += __shfl_xor_sync(0xffffffffu, a,  o);
        a2 += __shfl_xor_sync(0xffffffffu, a2, o);
    }
    __shared__ float s1[8], s2[8];
    if ((c & 31) == 0) { s1[c >> 5] = a; s2[c >> 5] = a2; }
    __syncthreads();
    float sum = 0.f, sq = 0.f;
    #pragma unroll
    for (int i = 0; i < 8; i++) { sum += s1[i]; sq += s2[i]; }
    float mu  = sum * (1.0f / D_MODEL);
    float var = sq * (1.0f / D_MODEL) - mu * mu;
    float rr  = rsqrtf(var + 1e-5f);
    float y   = (v - mu) * rr * gamma[c] + beta[c];
    g_h2H[(size_t)t * D_MODEL + c] = __float2half(y);
}

// ================= one-shot weight prep: W[K,N] -> fp16 [N][K] =================
__global__ void wprep_all(const float* __restrict__ Wv, const float* __restrict__ Wo,
                          const float* __restrict__ Wa, const float* __restrict__ Wout,
                          const float* __restrict__ Wf1, const float* __restrict__ Wf2) {
    int i = blockIdx.x * blockDim.x + threadIdx.x;
    const float* W; __half* B; int K, N, rowOff, i2;
    if (i < 65536)        { W = Wv;  B = w_v;  K = 256;  N = 256;  rowOff = 0;   i2 = i; }
    else if (i < 131072)  { W = Wo;  B = w_qa; K = 256;  N = 256;  rowOff = 0;   i2 = i - 65536; }
    else if (i < 163840)  { W = Wa;  B = w_qa; K = 256;  N = 128;  rowOff = 256; i2 = i - 131072; }
    else if (i < 229376)  { W = Wout;B = w_o;  K = 256;  N = 256;  rowOff = 0;   i2 = i - 163840; }
    else if (i < 491520)  { W = Wf1; B = w_f1; K = 256;  N = 1024; rowOff = 0;   i2 = i - 229376; }
    else if (i < 753664)  { W = Wf2; B = w_f2; K = 1024; N = 256;  rowOff = 0;   i2 = i - 491520; }
    else return;
    int k = i2 / N, n = i2 - k * N;
    B[(size_t)(n + rowOff) * K + k] = __float2half(W[i2]);
}

// ================= deform: full warp per point, 128B row-pair loads, one final combine =================
__global__ void deform_kernel(const float* __restrict__ ref) {
    const int lvH[4] = {128, 64, 32, 16};
    const int lvW[4] = {128, 64, 32, 16};
    const int lvS[4] = {0, 16384, 20480, 21504};

    int g = blockIdx.x * 8 + (threadIdx.x >> 5);
    int lane = threadIdx.x & 31;
    int b  = g / (SLEN * NHEADS);
    int rm = g - b * (SLEN * NHEADS);
    int qi = rm / NHEADS;
    int h  = rm - qi * NHEADS;
    int tok = b * SLEN + qi;

    // softmax over 16 logits (lanes 0..15)
    float lg = (lane < 16) ? g_attn[(size_t)tok * 128 + h * 16 + lane] : -1e30f;
    float mx = lg;
    #pragma unroll
    for (int o = 8; o; o >>= 1) mx = fmaxf(mx, __shfl_xor_sync(0xffffffffu, mx, o));
    float e = (lane < 16) ? __expf(lg - mx) : 0.f;
    float se = e;
    #pragma unroll
    for (int o = 8; o; o >>= 1) se += __shfl_xor_sync(0xffffffffu, se, o);
    float wnorm = e / se;

    const int xs = lane >> 4;          // 0 -> x0 column, 1 -> x1 column
    const int li = lane & 15;          // dim pair: (2li, 2li+1)

    float2 acc = make_float2(0.f, 0.f);
    #pragma unroll
    for (int lvl = 0; lvl < NLEV; lvl++) {
        const int Hh = lvH[lvl], Ww = lvW[lvl], st = lvS[lvl];
        float rx = ref[((size_t)tok * NLEV + lvl) * 2 + 0];
        float ry = ref[((size_t)tok * NLEV + lvl) * 2 + 1];
        const size_t pb = (size_t)h * NTOK + (size_t)(b * SLEN + st);
        #pragma unroll
        for (int p = 0; p < NPTS; p++) {
            const float* op = g_off + (size_t)tok * 256 + (((h * NLEV + lvl) * NPTS + p) * 2);
            float x = rx * (float)Ww + op[0] - 0.5f;
            float y = ry * (float)Hh + op[1] - 0.5f;
            float w = __shfl_sync(0xffffffffu, wnorm, lvl * 4 + p);

            float x0f = floorf(x), y0f = floorf(y);
            int x0 = (int)x0f, y0 = (int)y0f;
            float wx = x - x0f, wy = y - y0f;
            int xi = x0 + xs;
            int y1 = y0 + 1;
            float wxl = xs ? wx : (1.0f - wx);
            bool vx = (xi >= 0) & (xi < Ww);
            bool vy0 = (y0 >= 0) & (y0 < Hh);
            bool vy1 = (y1 >= 0) & (y1 < Hh);

            float2 v0 = make_float2(0.f, 0.f), v1 = v0;
            if (vx & vy0)
                v0 = __half22float2(*(const __half2*)&g_valueH[(pb + (size_t)y0 * Ww + xi) * 32 + li * 2]);
            if (vx & vy1)
                v1 = __half22float2(*(const __half2*)&g_valueH[(pb + (size_t)y1 * Ww + xi) * 32 + li * 2]);

            float w0 = w * wxl * (1.0f - wy);
            float w1 = w * wxl * wy;
            acc.x += v0.x * w0 + v1.x * w1;
            acc.y += v0.y * w0 + v1.y * w1;
        }
    }
    acc.x += __shfl_xor_sync(0xffffffffu, acc.x, 16);
    acc.y += __shfl_xor_sync(0xffffffffu, acc.y, 16);
    if (lane < 16) {
        __half2 hv = __floats2half2_rn(acc.x, acc.y);
        *(__half2*)&g_sampH[(size_t)tok * D_MODEL + h * HDIM + li * 2] = hv;
    }
}

// ================= launch =================
extern "C" void kernel_launch(void* const* d_in, const int* in_sizes, int n_in,
                              void* d_out, int out_size) {
    const float* src  = (const float*)d_in[0];
    const float* pos  = (const float*)d_in[1];
    const float* refp = (const float*)d_in[2];
    const float* n1g = (const float*)d_in[5];
    const float* n1b = (const float*)d_in[6];
    const float* n2g = (const float*)d_in[7];
    const float* n2b = (const float*)d_in[8];
    const float* Wv  = (const float*)d_in[9];
    const float* bv  = (const float*)d_in[10];
    const float* Wo  = (const float*)d_in[11];
    const float* bo  = (const float*)d_in[12];
    const float* Wa  = (const float*)d_in[13];
    const float* ba  = (const float*)d_in[14];
    const float* Wout= (const float*)d_in[15];
    const float* bout= (const float*)d_in[16];
    const float* Wf1 = (const float*)d_in[17];
    const float* bf1 = (const float*)d_in[18];
    const float* Wf2 = (const float*)d_in[19];
    const float* bf2 = (const float*)d_in[20];
    float* out = (float*)d_out;

    __half *srcH, *qH, *sampH, *h2H, *ffnH, *valH;
    __half *wv, *wqa, *wo, *wf1, *wf2;
    float *pOff, *pAttn, *pSrc2;
    cudaGetSymbolAddress((void**)&srcH, g_srcH);
    cudaGetSymbolAddress((void**)&qH,   g_qH);
    cudaGetSymbolAddress((void**)&sampH,g_sampH);
    cudaGetSymbolAddress((void**)&h2H,  g_h2H);
    cudaGetSymbolAddress((void**)&ffnH, g_ffnH);
    cudaGetSymbolAddress((void**)&valH, g_valueH);
    cudaGetSymbolAddress((void**)&wv,   w_v);
    cudaGetSymbolAddress((void**)&wqa,  w_qa);
    cudaGetSymbolAddress((void**)&wo,   w_o);
    cudaGetSymbolAddress((void**)&wf1,  w_f1);
    cudaGetSymbolAddress((void**)&wf2,  w_f2);
    cudaGetSymbolAddress((void**)&pOff,  g_off);
    cudaGetSymbolAddress((void**)&pAttn, g_attn);
    cudaGetSymbolAddress((void**)&pSrc2, g_src2);

    cudaFuncSetAttribute(mma_gemm<1>, cudaFuncAttributeMaxDynamicSharedMemorySize, GEMM_SMEM);
    cudaFuncSetAttribute(mma_gemm<2>, cudaFuncAttributeMaxDynamicSharedMemorySize, GEMM_SMEM);
    cudaFuncSetAttribute(mma_gemm<3>, cudaFuncAttributeMaxDynamicSharedMemorySize, GEMM_SMEM);
    cudaFuncSetAttribute(mma_gemm<4>, cudaFuncAttributeMaxDynamicSharedMemorySize, GEMM_SMEM);

    // side stream + events (created once; fork/join pattern is graph-capturable)
    static cudaStream_t s2 = nullptr;
    static cudaEvent_t evA = nullptr, evB = nullptr, evC = nullptr, evD = nullptr;
    if (!s2) {
        cudaStreamCreateWithFlags(&s2, cudaStreamNonBlocking);
        cudaEventCreateWithFlags(&evA, cudaEventDisableTiming);
        cudaEventCreateWithFlags(&evB, cudaEventDisableTiming);
        cudaEventCreateWithFlags(&evC, cudaEventDisableTiming);
        cudaEventCreateWithFlags(&evD, cudaEventDisableTiming);
    }

    dim3 t256(256);
    const int MB = NTOK / 128;   // 340

    // fork s2 off the main stream
    cudaEventRecord(evA, 0);
    cudaStreamWaitEvent(s2, evA, 0);

    wprep_all<<<(753664 + 255) / 256, t256, 0, s2>>>(Wv, Wo, Wa, Wout, Wf1, Wf2);
    cudaEventRecord(evB, s2);

    pre_kernel<<<NTOK, t256>>>(src, n1g, n1b, pos);
    cudaEventRecord(evC, 0);

    // value GEMM on main stream (needs srcH + w_v)
    cudaStreamWaitEvent(0, evB, 0);
    mma_gemm<4><<<dim3(1, MB), t256, GEMM_SMEM>>>(srcH, wv, bv, nullptr,
                                                  nullptr, nullptr, valH, 256, 256);
    // qa GEMM on s2 (needs qH + w_qa); N logical 384, padded to 512
    cudaStreamWaitEvent(s2, evC, 0);
    mma_gemm<3><<<dim3(2, MB), t256, GEMM_SMEM, s2>>>(qH, wqa, bo, ba,
                                                      pOff, pAttn, nullptr, 512, 256);
    cudaEventRecord(evD, s2);

    // join; deform needs value + off + attn
    cudaStreamWaitEvent(0, evD, 0);
    deform_kernel<<<(NTOK * NHEADS) / 8, t256>>>(refp);

    mma_gemm<2><<<dim3(1, MB), t256, GEMM_SMEM>>>(sampH, wo, bout, src,
                                                  pSrc2, nullptr, nullptr, 256, 256);
    ln2_kernel<<<NTOK, t256>>>(pSrc2, n2g, n2b);
    mma_gemm<1><<<dim3(4, MB), t256, GEMM_SMEM>>>(h2H, wf1, bf1, nullptr,
                                                  nullptr, nullptr, ffnH, 1024, 256);
    mma_gemm<2><<<dim3(1, MB), t256, GEMM_SMEM>>>(ffnH, wf2, bf2, pSrc2,
                                                  out, nullptr, nullptr, 256, 1024);
}

// round 9
// speedup vs baseline: 1.0972x; 1.0972x over previous
#include <cuda_runtime.h>
#include <cuda_fp16.h>
#include <math.h>
#include <stdint.h>

#define D_MODEL 256
#define D_FFN   1024
#define NHEADS  8
#define NLEV    4
#define NPTS    4
#define HDIM    32
#define BATCH   2
#define SLEN    21760
#define NTOK    (BATCH * SLEN)   // 43520

// ================= scratch (device globals; no allocation allowed) =================
__device__ __align__(16) __half g_srcH[NTOK * D_MODEL];
__device__ __align__(16) __half g_qH[NTOK * D_MODEL];
__device__ __align__(16) __half g_sampH[NTOK * D_MODEL];
__device__ __align__(16) __half g_h2H[NTOK * D_MODEL];
__device__ __align__(16) __half g_ffnH[NTOK * D_FFN];
__device__ __align__(16) __half g_valueH[NTOK * D_MODEL];     // planar: [h][tok][dim]

__device__ float g_off[NTOK * D_MODEL];
__device__ float g_attn[NTOK * NHEADS * 16];                  // raw logits
__device__ float g_src2[NTOK * D_MODEL];

// weights transposed [N][K], fp16
__device__ __align__(16) __half w_v[256 * 256];
__device__ __align__(16) __half w_qa[384 * 256];              // 0-255: W_off, 256-383: W_attn
__device__ __align__(16) __half w_o[256 * 256];
__device__ __align__(16) __half w_f1[1024 * 256];
__device__ __align__(16) __half w_f2[256 * 1024];

// ================= helpers =================
__device__ __forceinline__ uint32_t smem_u32(const void* p) {
    uint32_t a;
    asm("{ .reg .u64 t; cvta.to.shared.u64 t, %1; cvt.u32.u64 %0, t; }" : "=r"(a) : "l"(p));
    return a;
}
__device__ __forceinline__ void ldm_x4(uint32_t* r, uint32_t addr) {
    asm volatile("ldmatrix.sync.aligned.m8n8.x4.shared.b16 {%0,%1,%2,%3}, [%4];"
                 : "=r"(r[0]), "=r"(r[1]), "=r"(r[2]), "=r"(r[3]) : "r"(addr));
}
__device__ __forceinline__ void mma16816(float* d, const uint32_t* a, const uint32_t* b) {
    asm volatile("mma.sync.aligned.m16n8k16.row.col.f32.f16.f16.f32 "
                 "{%0,%1,%2,%3}, {%4,%5,%6,%7}, {%8,%9}, {%0,%1,%2,%3};"
                 : "+f"(d[0]), "+f"(d[1]), "+f"(d[2]), "+f"(d[3])
                 : "r"(a[0]), "r"(a[1]), "r"(a[2]), "r"(a[3]), "r"(b[0]), "r"(b[1]));
}
__device__ __forceinline__ void cpa16(uint32_t dst, const void* src) {
    asm volatile("cp.async.cg.shared.global [%0], [%1], 16;" :: "r"(dst), "l"(src));
}

// ================= fp16 HMMA GEMM (R6 config): CTA 128x128, 4 warps of 64x64 =================
// 128 threads, BK=64, 3-stage cp.async ring, 2 CTAs/SM.
// EPI: 1 = gelu(x+bias) -> fp16; 2 = x+bias+aux(residual) -> fp32;
//      3 = dual (N=384): col<256 -> C(bias), col>=256 -> Cb(aux bias);
//      4 = fp16 planar value: Ch[((col>>5)*NTOK+row)*32 + (col&31)]
static const int LDSB = 144;                  // 64 fp16 (128 B) + 16 B pad
static const int BUFB = 128 * LDSB;           // 18432 B
static const int GEMM_SMEM = 6 * BUFB;        // 110592 B

template <int EPI>
__global__ void __launch_bounds__(128, 2) mma_gemm(
    const __half* __restrict__ A, const __half* __restrict__ B,
    const float* __restrict__ bias, const float* __restrict__ aux,
    float* __restrict__ C, float* __restrict__ Cb, __half* __restrict__ Ch,
    int N, int K)
{
    extern __shared__ __align__(16) char sm[];
    const uint32_t smb = smem_u32(sm);
    const int tid = threadIdx.x;
    const int wid = tid >> 5, lane = tid & 31;
    const int wm = wid >> 1, wn = wid & 1;                // 2x2 warps of 64x64
    const int m0 = blockIdx.y * 128, n0 = blockIdx.x * 128;
    const int S = K >> 6;

    float acc[4][8][4];
    #pragma unroll
    for (int i = 0; i < 4; i++)
        #pragma unroll
        for (int j = 0; j < 8; j++)
            #pragma unroll
            for (int r = 0; r < 4; r++) acc[i][j][r] = 0.f;

    auto prefetch = [&](int s) {
        int k0 = s << 6;
        const uint32_t ab = smb + (uint32_t)(s % 3) * (2u * BUFB);
        const uint32_t bb = ab + BUFB;
        #pragma unroll
        for (int i = 0; i < 16; i++) {
            int c = tid + (i << 7);                       // 0..2047
            int cc = c & 1023;
            int row = cc >> 3;
            int kc  = (cc & 7) << 3;
            uint32_t dst; const __half* src;
            if (c < 1024) {
                dst = ab + (uint32_t)(row * LDSB + kc * 2);
                src = A + (size_t)(m0 + row) * K + k0 + kc;
            } else {
                dst = bb + (uint32_t)(row * LDSB + kc * 2);
                src = B + (size_t)(n0 + row) * K + k0 + kc;
            }
            cpa16(dst, src);
        }
        asm volatile("cp.async.commit_group;");
    };

    prefetch(0);
    if (S > 1) prefetch(1);

    for (int s = 0; s < S; s++) {
        if (s + 1 < S) asm volatile("cp.async.wait_group 1;");
        else           asm volatile("cp.async.wait_group 0;");
        __syncthreads();
        if (s + 2 < S) prefetch(s + 2);

        const uint32_t ab = smb + (uint32_t)(s % 3) * (2u * BUFB);
        const uint32_t bb = ab + BUFB;
        const uint32_t aoff = ab + (uint32_t)(((lane & 15) + wm * 64) * LDSB + ((lane >> 4) << 4));
        const uint32_t boff = bb + (uint32_t)((((lane & 7) + ((lane >> 4) << 3)) + wn * 64) * LDSB
                                              + (((lane >> 3) & 1) << 4));
        #pragma unroll
        for (int ks = 0; ks < 4; ks++) {
            const uint32_t kb = (uint32_t)(ks << 5);
            uint32_t afr[4][4], bfr[8][2];
            #pragma unroll
            for (int mi = 0; mi < 4; mi++)
                ldm_x4(afr[mi], aoff + (uint32_t)(mi * 16 * LDSB) + kb);
            #pragma unroll
            for (int nj = 0; nj < 4; nj++) {
                uint32_t r[4];
                ldm_x4(r, boff + (uint32_t)(nj * 16 * LDSB) + kb);
                bfr[nj * 2][0] = r[0]; bfr[nj * 2][1] = r[1];
                bfr[nj * 2 + 1][0] = r[2]; bfr[nj * 2 + 1][1] = r[3];
            }
            #pragma unroll
            for (int mi = 0; mi < 4; mi++)
                #pragma unroll
                for (int ni = 0; ni < 8; ni++)
                    mma16816(acc[mi][ni], afr[mi], bfr[ni]);
        }
    }
    __syncthreads();

    // ---- epilogue: stage 64x64 per warp in smem (stride 68 floats), store coalesced ----
    float* ws = (float*)sm + wid * (64 * 68);
    const int er = lane >> 2, ec = (lane & 3) * 2;
    #pragma unroll
    for (int mi = 0; mi < 4; mi++)
        #pragma unroll
        for (int ni = 0; ni < 8; ni++) {
            *(float2*)&ws[(mi * 16 + er) * 68 + ni * 8 + ec]     = make_float2(acc[mi][ni][0], acc[mi][ni][1]);
            *(float2*)&ws[(mi * 16 + er + 8) * 68 + ni * 8 + ec] = make_float2(acc[mi][ni][2], acc[mi][ni][3]);
        }
    __syncwarp();

    const int gc0 = n0 + wn * 64 + lane;
    const int gc1 = gc0 + 32;
    float b0, b1;
    if (EPI == 3) {
        b0 = (gc0 < 256) ? bias[gc0] : aux[gc0 - 256];
        b1 = (gc1 < 256) ? bias[gc1] : aux[gc1 - 256];
    } else { b0 = bias[gc0]; b1 = bias[gc1]; }

    for (int r = 0; r < 64; r++) {
        const int gr = m0 + wm * 64 + r;
        float v0 = ws[r * 68 + lane] + b0;
        float v1 = ws[r * 68 + 32 + lane] + b1;
        if (EPI == 1) {
            v0 = 0.5f * v0 * (1.0f + erff(v0 * 0.70710678118654752f));
            v1 = 0.5f * v1 * (1.0f + erff(v1 * 0.70710678118654752f));
            Ch[(size_t)gr * N + gc0] = __float2half(v0);
            Ch[(size_t)gr * N + gc1] = __float2half(v1);
        } else if (EPI == 2) {
            C[(size_t)gr * N + gc0] = v0 + aux[(size_t)gr * N + gc0];
            C[(size_t)gr * N + gc1] = v1 + aux[(size_t)gr * N + gc1];
        } else if (EPI == 3) {
            if (gc0 < 256) C[(size_t)gr * 256 + gc0] = v0;
            else           Cb[(size_t)gr * 128 + (gc0 - 256)] = v0;
            if (gc1 < 256) C[(size_t)gr * 256 + gc1] = v1;
            else           Cb[(size_t)gr * 128 + (gc1 - 256)] = v1;
        } else {  // EPI == 4: planar value
            Ch[((size_t)(gc0 >> 5) * NTOK + gr) * 32 + (gc0 & 31)] = __float2half(v0);
            Ch[((size_t)(gc1 >> 5) * NTOK + gr) * 32 + (gc1 & 31)] = __float2half(v1);
        }
    }
}

// ================= fused prep: src -> fp16; q = LN1(src)+pos -> fp16 =================
__global__ void pre_kernel(const float* __restrict__ x,
                           const float* __restrict__ gamma,
                           const float* __restrict__ beta,
                           const float* __restrict__ pos) {
    int t = blockIdx.x;
    int c = threadIdx.x;
    float v = x[t * D_MODEL + c];
    g_srcH[(size_t)t * D_MODEL + c] = __float2half(v);
    float a = v, a2 = v * v;
    #pragma unroll
    for (int o = 16; o; o >>= 1) {
        a  += __shfl_xor_sync(0xffffffffu, a,  o);
        a2 += __shfl_xor_sync(0xffffffffu, a2, o);
    }
    __shared__ float s1[8], s2[8];
    if ((c & 31) == 0) { s1[c >> 5] = a; s2[c >> 5] = a2; }
    __syncthreads();
    float sum = 0.f, sq = 0.f;
    #pragma unroll
    for (int i = 0; i < 8; i++) { sum += s1[i]; sq += s2[i]; }
    float mu  = sum * (1.0f / D_MODEL);
    float var = sq * (1.0f / D_MODEL) - mu * mu;
    float rr  = rsqrtf(var + 1e-5f);
    float y   = (v - mu) * rr * gamma[c] + beta[c] + pos[t * D_MODEL + c];
    g_qH[(size_t)t * D_MODEL + c] = __float2half(y);
}

// ================= layernorm2 -> fp16 =================
__global__ void ln2_kernel(const float* __restrict__ x,
                           const float* __restrict__ gamma,
                           const float* __restrict__ beta) {
    int t = blockIdx.x;
    int c = threadIdx.x;
    float v = x[t * D_MODEL + c];
    float a = v, a2 = v * v;
    #pragma unroll
    for (int o = 16; o; o >>= 1) {
        a  += __shfl_xor_sync(0xffffffffu, a,  o);
        a2 += __shfl_xor_sync(0xffffffffu, a2, o);
    }
    __shared__ float s1[8], s2[8];
    if ((c & 31) == 0) { s1[c >> 5] = a; s2[c >> 5] = a2; }
    __syncthreads();
    float sum = 0.f, sq = 0.f;
    #pragma unroll
    for (int i = 0; i < 8; i++) { sum += s1[i]; sq += s2[i]; }
    float mu  = sum * (1.0f / D_MODEL);
    float var = sq * (1.0f / D_MODEL) - mu * mu;
    float rr  = rsqrtf(var + 1e-5f);
    float y   = (v - mu) * rr * gamma[c] + beta[c];
    g_h2H[(size_t)t * D_MODEL + c] = __float2half(y);
}

// ================= one-shot weight prep: W[K,N] -> fp16 [N][K] =================
__global__ void wprep_all(const float* __restrict__ Wv, const float* __restrict__ Wo,
                          const float* __restrict__ Wa, const float* __restrict__ Wout,
                          const float* __restrict__ Wf1, const float* __restrict__ Wf2) {
    int i = blockIdx.x * blockDim.x + threadIdx.x;
    const float* W; __half* B; int K, N, rowOff, i2;
    if (i < 65536)        { W = Wv;  B = w_v;  K = 256;  N = 256;  rowOff = 0;   i2 = i; }
    else if (i < 131072)  { W = Wo;  B = w_qa; K = 256;  N = 256;  rowOff = 0;   i2 = i - 65536; }
    else if (i < 163840)  { W = Wa;  B = w_qa; K = 256;  N = 128;  rowOff = 256; i2 = i - 131072; }
    else if (i < 229376)  { W = Wout;B = w_o;  K = 256;  N = 256;  rowOff = 0;   i2 = i - 163840; }
    else if (i < 491520)  { W = Wf1; B = w_f1; K = 256;  N = 1024; rowOff = 0;   i2 = i - 229376; }
    else if (i < 753664)  { W = Wf2; B = w_f2; K = 1024; N = 256;  rowOff = 0;   i2 = i - 491520; }
    else return;
    int k = i2 / N, n = i2 - k * N;
    B[(size_t)(n + rowOff) * K + k] = __float2half(W[i2]);
}

// ================= deform v3: all scalars prefetched to registers, shfl-distributed =================
// One warp per (tok, h). Lanes 0-15: x0 column / dim pairs; lanes 16-31: x1 column.
__global__ void deform_kernel(const float* __restrict__ ref) {
    const int lvH[4] = {128, 64, 32, 16};
    const int lvW[4] = {128, 64, 32, 16};
    const int lvS[4] = {0, 16384, 20480, 21504};

    int g = blockIdx.x * 8 + (threadIdx.x >> 5);
    int lane = threadIdx.x & 31;
    int b  = g / (SLEN * NHEADS);
    int rm = g - b * (SLEN * NHEADS);
    int qi = rm / NHEADS;
    int h  = rm - qi * NHEADS;
    int tok = b * SLEN + qi;

    // --- prefetch everything scalar in 3 coalesced/broadcast loads ---
    float offv = g_off[(size_t)tok * 256 + h * 32 + lane];            // 32 offsets (x,y interleaved)
    float refv = (lane < 8) ? ref[(size_t)tok * 8 + lane] : 0.f;      // 4 levels x (x,y)
    float lg   = (lane < 16) ? g_attn[(size_t)tok * 128 + h * 16 + lane] : -1e30f;

    // softmax over the 16 logits
    float mx = lg;
    #pragma unroll
    for (int o = 8; o; o >>= 1) mx = fmaxf(mx, __shfl_xor_sync(0xffffffffu, mx, o));
    float e = (lane < 16) ? __expf(lg - mx) : 0.f;
    float se = e;
    #pragma unroll
    for (int o = 8; o; o >>= 1) se += __shfl_xor_sync(0xffffffffu, se, o);
    float wnorm = e / se;

    const int xs = lane >> 4;          // 0 -> x0 column, 1 -> x1 column
    const int li = lane & 15;          // dim pair: (2li, 2li+1)

    float2 acc = make_float2(0.f, 0.f);
    #pragma unroll
    for (int lvl = 0; lvl < NLEV; lvl++) {
        const int Hh = lvH[lvl], Ww = lvW[lvl], st = lvS[lvl];
        const float rx = __shfl_sync(0xffffffffu, refv, lvl * 2 + 0);
        const float ry = __shfl_sync(0xffffffffu, refv, lvl * 2 + 1);
        const size_t pb = (size_t)h * NTOK + (size_t)(b * SLEN + st);
        #pragma unroll
        for (int p = 0; p < NPTS; p++) {
            const int sidx = lvl * 4 + p;
            float ox = __shfl_sync(0xffffffffu, offv, sidx * 2 + 0);
            float oy = __shfl_sync(0xffffffffu, offv, sidx * 2 + 1);
            float w  = __shfl_sync(0xffffffffu, wnorm, sidx);

            float x = rx * (float)Ww + ox - 0.5f;
            float y = ry * (float)Hh + oy - 0.5f;
            float x0f = floorf(x), y0f = floorf(y);
            int x0 = (int)x0f, y0 = (int)y0f;
            float wx = x - x0f, wy = y - y0f;
            int xi = x0 + xs;
            int y1 = y0 + 1;
            float wxl = xs ? wx : (1.0f - wx);
            bool vx  = (xi >= 0) & (xi < Ww);
            bool vy0 = (y0 >= 0) & (y0 < Hh);
            bool vy1 = (y1 >= 0) & (y1 < Hh);

            float2 v0 = make_float2(0.f, 0.f), v1 = v0;
            if (vx & vy0)
                v0 = __half22float2(*(const __half2*)&g_valueH[(pb + (size_t)y0 * Ww + xi) * 32 + li * 2]);
            if (vx & vy1)
                v1 = __half22float2(*(const __half2*)&g_valueH[(pb + (size_t)y1 * Ww + xi) * 32 + li * 2]);

            float w0 = w * wxl * (1.0f - wy);
            float w1 = w * wxl * wy;
            acc.x += v0.x * w0 + v1.x * w1;
            acc.y += v0.y * w0 + v1.y * w1;
        }
    }
    acc.x += __shfl_xor_sync(0xffffffffu, acc.x, 16);
    acc.y += __shfl_xor_sync(0xffffffffu, acc.y, 16);
    if (lane < 16) {
        __half2 hv = __floats2half2_rn(acc.x, acc.y);
        *(__half2*)&g_sampH[(size_t)tok * D_MODEL + h * HDIM + li * 2] = hv;
    }
}

// ================= launch =================
extern "C" void kernel_launch(void* const* d_in, const int* in_sizes, int n_in,
                              void* d_out, int out_size) {
    const float* src  = (const float*)d_in[0];
    const float* pos  = (const float*)d_in[1];
    const float* refp = (const float*)d_in[2];
    const float* n1g = (const float*)d_in[5];
    const float* n1b = (const float*)d_in[6];
    const float* n2g = (const float*)d_in[7];
    const float* n2b = (const float*)d_in[8];
    const float* Wv  = (const float*)d_in[9];
    const float* bv  = (const float*)d_in[10];
    const float* Wo  = (const float*)d_in[11];
    const float* bo  = (const float*)d_in[12];
    const float* Wa  = (const float*)d_in[13];
    const float* ba  = (const float*)d_in[14];
    const float* Wout= (const float*)d_in[15];
    const float* bout= (const float*)d_in[16];
    const float* Wf1 = (const float*)d_in[17];
    const float* bf1 = (const float*)d_in[18];
    const float* Wf2 = (const float*)d_in[19];
    const float* bf2 = (const float*)d_in[20];
    float* out = (float*)d_out;

    __half *srcH, *qH, *sampH, *h2H, *ffnH, *valH;
    __half *wv, *wqa, *wo, *wf1, *wf2;
    float *pOff, *pAttn, *pSrc2;
    cudaGetSymbolAddress((void**)&srcH, g_srcH);
    cudaGetSymbolAddress((void**)&qH,   g_qH);
    cudaGetSymbolAddress((void**)&sampH,g_sampH);
    cudaGetSymbolAddress((void**)&h2H,  g_h2H);
    cudaGetSymbolAddress((void**)&ffnH, g_ffnH);
    cudaGetSymbolAddress((void**)&valH, g_valueH);
    cudaGetSymbolAddress((void**)&wv,   w_v);
    cudaGetSymbolAddress((void**)&wqa,  w_qa);
    cudaGetSymbolAddress((void**)&wo,   w_o);
    cudaGetSymbolAddress((void**)&wf1,  w_f1);
    cudaGetSymbolAddress((void**)&wf2,  w_f2);
    cudaGetSymbolAddress((void**)&pOff,  g_off);
    cudaGetSymbolAddress((void**)&pAttn, g_attn);
    cudaGetSymbolAddress((void**)&pSrc2, g_src2);

    cudaFuncSetAttribute(mma_gemm<1>, cudaFuncAttributeMaxDynamicSharedMemorySize, GEMM_SMEM);
    cudaFuncSetAttribute(mma_gemm<2>, cudaFuncAttributeMaxDynamicSharedMemorySize, GEMM_SMEM);
    cudaFuncSetAttribute(mma_gemm<3>, cudaFuncAttributeMaxDynamicSharedMemorySize, GEMM_SMEM);
    cudaFuncSetAttribute(mma_gemm<4>, cudaFuncAttributeMaxDynamicSharedMemorySize, GEMM_SMEM);

    dim3 t256(256), t128(128);
    const int MB = NTOK / 128;   // 340

    wprep_all<<<(753664 + 255) / 256, t256>>>(Wv, Wo, Wa, Wout, Wf1, Wf2);          // 0
    pre_kernel<<<NTOK, t256>>>(src, n1g, n1b, pos);                                 // 1
    mma_gemm<4><<<dim3(2, MB), t128, GEMM_SMEM>>>(srcH, wv, bv, nullptr,            // 2: value (planar)
                                                  nullptr, nullptr, valH, 256, 256);
    mma_gemm<3><<<dim3(3, MB), t128, GEMM_SMEM>>>(qH, wqa, bo, ba,                  // 3: offsets+logits
                                                  pOff, pAttn, nullptr, 384, 256);
    deform_kernel<<<(NTOK * NHEADS) / 8, t256>>>(refp);                             // 4
    mma_gemm<2><<<dim3(2, MB), t128, GEMM_SMEM>>>(sampH, wo, bout, src,             // 5: out-proj + res
                                                  pSrc2, nullptr, nullptr, 256, 256);
    ln2_kernel<<<NTOK, t256>>>(pSrc2, n2g, n2b);                                    // 6
    mma_gemm<1><<<dim3(8, MB), t128, GEMM_SMEM>>>(h2H, wf1, bf1, nullptr,           // 7: FFN1 + gelu
                                                  nullptr, nullptr, ffnH, 1024, 256);
    mma_gemm<2><<<dim3(2, MB), t128, GEMM_SMEM>>>(ffnH, wf2, bf2, pSrc2,            // 8: FFN2 + res
                                                  out, nullptr, nullptr, 256, 1024);
}

// round 10
// speedup vs baseline: 1.1496x; 1.0478x over previous
#include <cuda_runtime.h>
#include <cuda_fp16.h>
#include <math.h>
#include <stdint.h>

#define D_MODEL 256
#define D_FFN   1024
#define NHEADS  8
#define NLEV    4
#define NPTS    4
#define HDIM    32
#define BATCH   2
#define SLEN    21760
#define NTOK    (BATCH * SLEN)   // 43520

// ================= scratch (device globals; no allocation allowed) =================
__device__ __align__(16) __half g_srcH[NTOK * D_MODEL];
__device__ __align__(16) __half g_qH[NTOK * D_MODEL];
__device__ __align__(16) __half g_sampH[NTOK * D_MODEL];
__device__ __align__(16) __half g_h2H[NTOK * D_MODEL];
__device__ __align__(16) __half g_ffnH[NTOK * D_FFN];
__device__ __align__(16) __half g_valueH[NTOK * D_MODEL];     // planar: [h][tok][dim]

__device__ float g_off[NTOK * D_MODEL];
__device__ float g_attn[NTOK * NHEADS * 16];                  // raw logits
__device__ float g_src2[NTOK * D_MODEL];

// weights transposed [N][K], fp16
__device__ __align__(16) __half w_v[256 * 256];
__device__ __align__(16) __half w_qa[384 * 256];              // 0-255: W_off, 256-383: W_attn
__device__ __align__(16) __half w_o[256 * 256];
__device__ __align__(16) __half w_f1[1024 * 256];
__device__ __align__(16) __half w_f2[256 * 1024];

// ================= helpers =================
__device__ __forceinline__ uint32_t smem_u32(const void* p) {
    uint32_t a;
    asm("{ .reg .u64 t; cvta.to.shared.u64 t, %1; cvt.u32.u64 %0, t; }" : "=r"(a) : "l"(p));
    return a;
}
__device__ __forceinline__ void ldm_x4(uint32_t* r, uint32_t addr) {
    asm volatile("ldmatrix.sync.aligned.m8n8.x4.shared.b16 {%0,%1,%2,%3}, [%4];"
                 : "=r"(r[0]), "=r"(r[1]), "=r"(r[2]), "=r"(r[3]) : "r"(addr));
}
__device__ __forceinline__ void mma16816(float* d, const uint32_t* a, const uint32_t* b) {
    asm volatile("mma.sync.aligned.m16n8k16.row.col.f32.f16.f16.f32 "
                 "{%0,%1,%2,%3}, {%4,%5,%6,%7}, {%8,%9}, {%0,%1,%2,%3};"
                 : "+f"(d[0]), "+f"(d[1]), "+f"(d[2]), "+f"(d[3])
                 : "r"(a[0]), "r"(a[1]), "r"(a[2]), "r"(a[3]), "r"(b[0]), "r"(b[1]));
}
__device__ __forceinline__ void cpa16(uint32_t dst, const void* src) {
    asm volatile("cp.async.cg.shared.global [%0], [%1], 16;" :: "r"(dst), "l"(src));
}

// ================= fp16 HMMA GEMM (R6 config): CTA 128x128, 4 warps of 64x64 =================
// 128 threads, BK=64, 3-stage cp.async ring, 2 CTAs/SM.
// EPI: 1 = gelu(x+bias) -> fp16; 2 = x+bias+aux(residual) -> fp32;
//      3 = dual (N=384): col<256 -> C(bias), col>=256 -> Cb(aux bias);
//      4 = fp16 planar value: Ch[((col>>5)*NTOK+row)*32 + (col&31)]
static const int LDSB = 144;                  // 64 fp16 (128 B) + 16 B pad
static const int BUFB = 128 * LDSB;           // 18432 B
static const int GEMM_SMEM = 6 * BUFB;        // 110592 B

template <int EPI>
__global__ void __launch_bounds__(128, 2) mma_gemm(
    const __half* __restrict__ A, const __half* __restrict__ B,
    const float* __restrict__ bias, const float* __restrict__ aux,
    float* __restrict__ C, float* __restrict__ Cb, __half* __restrict__ Ch,
    int N, int K)
{
    extern __shared__ __align__(16) char sm[];
    const uint32_t smb = smem_u32(sm);
    const int tid = threadIdx.x;
    const int wid = tid >> 5, lane = tid & 31;
    const int wm = wid >> 1, wn = wid & 1;                // 2x2 warps of 64x64
    const int m0 = blockIdx.y * 128, n0 = blockIdx.x * 128;
    const int S = K >> 6;

    float acc[4][8][4];
    #pragma unroll
    for (int i = 0; i < 4; i++)
        #pragma unroll
        for (int j = 0; j < 8; j++)
            #pragma unroll
            for (int r = 0; r < 4; r++) acc[i][j][r] = 0.f;

    auto prefetch = [&](int s) {
        int k0 = s << 6;
        const uint32_t ab = smb + (uint32_t)(s % 3) * (2u * BUFB);
        const uint32_t bb = ab + BUFB;
        #pragma unroll
        for (int i = 0; i < 16; i++) {
            int c = tid + (i << 7);                       // 0..2047
            int cc = c & 1023;
            int row = cc >> 3;
            int kc  = (cc & 7) << 3;
            uint32_t dst; const __half* src;
            if (c < 1024) {
                dst = ab + (uint32_t)(row * LDSB + kc * 2);
                src = A + (size_t)(m0 + row) * K + k0 + kc;
            } else {
                dst = bb + (uint32_t)(row * LDSB + kc * 2);
                src = B + (size_t)(n0 + row) * K + k0 + kc;
            }
            cpa16(dst, src);
        }
        asm volatile("cp.async.commit_group;");
    };

    prefetch(0);
    if (S > 1) prefetch(1);

    for (int s = 0; s < S; s++) {
        if (s + 1 < S) asm volatile("cp.async.wait_group 1;");
        else           asm volatile("cp.async.wait_group 0;");
        __syncthreads();
        if (s + 2 < S) prefetch(s + 2);

        const uint32_t ab = smb + (uint32_t)(s % 3) * (2u * BUFB);
        const uint32_t bb = ab + BUFB;
        const uint32_t aoff = ab + (uint32_t)(((lane & 15) + wm * 64) * LDSB + ((lane >> 4) << 4));
        const uint32_t boff = bb + (uint32_t)((((lane & 7) + ((lane >> 4) << 3)) + wn * 64) * LDSB
                                              + (((lane >> 3) & 1) << 4));
        #pragma unroll
        for (int ks = 0; ks < 4; ks++) {
            const uint32_t kb = (uint32_t)(ks << 5);
            uint32_t afr[4][4], bfr[8][2];
            #pragma unroll
            for (int mi = 0; mi < 4; mi++)
                ldm_x4(afr[mi], aoff + (uint32_t)(mi * 16 * LDSB) + kb);
            #pragma unroll
            for (int nj = 0; nj < 4; nj++) {
                uint32_t r[4];
                ldm_x4(r, boff + (uint32_t)(nj * 16 * LDSB) + kb);
                bfr[nj * 2][0] = r[0]; bfr[nj * 2][1] = r[1];
                bfr[nj * 2 + 1][0] = r[2]; bfr[nj * 2 + 1][1] = r[3];
            }
            #pragma unroll
            for (int mi = 0; mi < 4; mi++)
                #pragma unroll
                for (int ni = 0; ni < 8; ni++)
                    mma16816(acc[mi][ni], afr[mi], bfr[ni]);
        }
    }
    __syncthreads();

    // ---- epilogue: stage 64x64 per warp in smem (stride 68 floats), store coalesced ----
    float* ws = (float*)sm + wid * (64 * 68);
    const int er = lane >> 2, ec = (lane & 3) * 2;
    #pragma unroll
    for (int mi = 0; mi < 4; mi++)
        #pragma unroll
        for (int ni = 0; ni < 8; ni++) {
            *(float2*)&ws[(mi * 16 + er) * 68 + ni * 8 + ec]     = make_float2(acc[mi][ni][0], acc[mi][ni][1]);
            *(float2*)&ws[(mi * 16 + er + 8) * 68 + ni * 8 + ec] = make_float2(acc[mi][ni][2], acc[mi][ni][3]);
        }
    __syncwarp();

    const int gc0 = n0 + wn * 64 + lane;
    const int gc1 = gc0 + 32;
    float b0, b1;
    if (EPI == 3) {
        b0 = (gc0 < 256) ? bias[gc0] : aux[gc0 - 256];
        b1 = (gc1 < 256) ? bias[gc1] : aux[gc1 - 256];
    } else { b0 = bias[gc0]; b1 = bias[gc1]; }

    for (int r = 0; r < 64; r++) {
        const int gr = m0 + wm * 64 + r;
        float v0 = ws[r * 68 + lane] + b0;
        float v1 = ws[r * 68 + 32 + lane] + b1;
        if (EPI == 1) {
            v0 = 0.5f * v0 * (1.0f + erff(v0 * 0.70710678118654752f));
            v1 = 0.5f * v1 * (1.0f + erff(v1 * 0.70710678118654752f));
            Ch[(size_t)gr * N + gc0] = __float2half(v0);
            Ch[(size_t)gr * N + gc1] = __float2half(v1);
        } else if (EPI == 2) {
            C[(size_t)gr * N + gc0] = v0 + aux[(size_t)gr * N + gc0];
            C[(size_t)gr * N + gc1] = v1 + aux[(size_t)gr * N + gc1];
        } else if (EPI == 3) {
            if (gc0 < 256) C[(size_t)gr * 256 + gc0] = v0;
            else           Cb[(size_t)gr * 128 + (gc0 - 256)] = v0;
            if (gc1 < 256) C[(size_t)gr * 256 + gc1] = v1;
            else           Cb[(size_t)gr * 128 + (gc1 - 256)] = v1;
        } else {  // EPI == 4: planar value
            Ch[((size_t)(gc0 >> 5) * NTOK + gr) * 32 + (gc0 & 31)] = __float2half(v0);
            Ch[((size_t)(gc1 >> 5) * NTOK + gr) * 32 + (gc1 & 31)] = __float2half(v1);
        }
    }
}

// ================= fused prep: src->fp16, q=LN1(src)+pos->fp16, AND weight prep =================
// Blocks < 2944 additionally convert one 256-element chunk of the weights.
__global__ void pre_kernel(const float* __restrict__ x,
                           const float* __restrict__ gamma,
                           const float* __restrict__ beta,
                           const float* __restrict__ pos,
                           const float* __restrict__ Wv, const float* __restrict__ Wo,
                           const float* __restrict__ Wa, const float* __restrict__ Wout,
                           const float* __restrict__ Wf1, const float* __restrict__ Wf2) {
    int t = blockIdx.x;
    int c = threadIdx.x;

    // ---- weight prep slice (first 2944 blocks; 753664 = 2944*256 elements total) ----
    int i = t * 256 + c;
    if (i < 753664) {
        const float* W; __half* B; int K, N, rowOff, i2;
        if (i < 65536)        { W = Wv;  B = w_v;  K = 256;  N = 256;  rowOff = 0;   i2 = i; }
        else if (i < 131072)  { W = Wo;  B = w_qa; K = 256;  N = 256;  rowOff = 0;   i2 = i - 65536; }
        else if (i < 163840)  { W = Wa;  B = w_qa; K = 256;  N = 128;  rowOff = 256; i2 = i - 131072; }
        else if (i < 229376)  { W = Wout;B = w_o;  K = 256;  N = 256;  rowOff = 0;   i2 = i - 163840; }
        else if (i < 491520)  { W = Wf1; B = w_f1; K = 256;  N = 1024; rowOff = 0;   i2 = i - 229376; }
        else                  { W = Wf2; B = w_f2; K = 1024; N = 256;  rowOff = 0;   i2 = i - 491520; }
        int k = i2 / N, n = i2 - k * N;
        B[(size_t)(n + rowOff) * K + k] = __float2half(W[i2]);
    }

    // ---- per-token prep ----
    float v = x[t * D_MODEL + c];
    g_srcH[(size_t)t * D_MODEL + c] = __float2half(v);
    float a = v, a2 = v * v;
    #pragma unroll
    for (int o = 16; o; o >>= 1) {
        a  += __shfl_xor_sync(0xffffffffu, a,  o);
        a2 += __shfl_xor_sync(0xffffffffu, a2, o);
    }
    __shared__ float s1[8], s2[8];
    if ((c & 31) == 0) { s1[c >> 5] = a; s2[c >> 5] = a2; }
    __syncthreads();
    float sum = 0.f, sq = 0.f;
    #pragma unroll
    for (int j = 0; j < 8; j++) { sum += s1[j]; sq += s2[j]; }
    float mu  = sum * (1.0f / D_MODEL);
    float var = sq * (1.0f / D_MODEL) - mu * mu;
    float rr  = rsqrtf(var + 1e-5f);
    float y   = (v - mu) * rr * gamma[c] + beta[c] + pos[t * D_MODEL + c];
    g_qH[(size_t)t * D_MODEL + c] = __float2half(y);
}

// ================= layernorm2 -> fp16 =================
__global__ void ln2_kernel(const float* __restrict__ x,
                           const float* __restrict__ gamma,
                           const float* __restrict__ beta) {
    int t = blockIdx.x;
    int c = threadIdx.x;
    float v = x[t * D_MODEL + c];
    float a = v, a2 = v * v;
    #pragma unroll
    for (int o = 16; o; o >>= 1) {
        a  += __shfl_xor_sync(0xffffffffu, a,  o);
        a2 += __shfl_xor_sync(0xffffffffu, a2, o);
    }
    __shared__ float s1[8], s2[8];
    if ((c & 31) == 0) { s1[c >> 5] = a; s2[c >> 5] = a2; }
    __syncthreads();
    float sum = 0.f, sq = 0.f;
    #pragma unroll
    for (int i = 0; i < 8; i++) { sum += s1[i]; sq += s2[i]; }
    float mu  = sum * (1.0f / D_MODEL);
    float var = sq * (1.0f / D_MODEL) - mu * mu;
    float rr  = rsqrtf(var + 1e-5f);
    float y   = (v - mu) * rr * gamma[c] + beta[c];
    g_h2H[(size_t)t * D_MODEL + c] = __float2half(y);
}

// ================= deform (R6 layout + scalar prefetch): 2 points/warp, half-warp per point =================
__global__ void deform_kernel(const float* __restrict__ ref) {
    const int lvH[4] = {128, 64, 32, 16};
    const int lvW[4] = {128, 64, 32, 16};
    const int lvS[4] = {0, 16384, 20480, 21504};

    int g = blockIdx.x * 8 + (threadIdx.x >> 5);
    int lane = threadIdx.x & 31;
    int b  = g / (SLEN * NHEADS);
    int rm = g - b * (SLEN * NHEADS);
    int qi = rm / NHEADS;
    int h  = rm - qi * NHEADS;
    int tok = b * SLEN + qi;

    // --- scalar prefetch: 32 offsets, 8 ref floats, 16 logits ---
    float offv = g_off[(size_t)tok * 256 + h * 32 + lane];
    float refv = (lane < 8) ? ref[(size_t)tok * 8 + lane] : 0.f;
    float lg   = (lane < 16) ? g_attn[(size_t)tok * 128 + h * 16 + lane] : -1e30f;

    float mx = lg;
    #pragma unroll
    for (int o = 8; o; o >>= 1) mx = fmaxf(mx, __shfl_xor_sync(0xffffffffu, mx, o));
    float e = (lane < 16) ? __expf(lg - mx) : 0.f;
    float se = e;
    #pragma unroll
    for (int o = 8; o; o >>= 1) se += __shfl_xor_sync(0xffffffffu, se, o);
    float wnorm = e / se;

    const int half = lane >> 4;        // which point of the pair
    const int li   = lane & 15;        // dim pair: (2li, 2li+1)

    float2 acc = make_float2(0.f, 0.f);
    #pragma unroll
    for (int lvl = 0; lvl < NLEV; lvl++) {
        const int Hh = lvH[lvl], Ww = lvW[lvl], st = lvS[lvl];
        const float rx = __shfl_sync(0xffffffffu, refv, lvl * 2 + 0);
        const float ry = __shfl_sync(0xffffffffu, refv, lvl * 2 + 1);
        const size_t pb = (size_t)h * NTOK + (size_t)(b * SLEN + st);
        #pragma unroll
        for (int ps = 0; ps < NPTS; ps += 2) {
            const int p = ps + half;
            const int sidx = lvl * 4 + p;
            float ox = __shfl_sync(0xffffffffu, offv, sidx * 2 + 0);
            float oy = __shfl_sync(0xffffffffu, offv, sidx * 2 + 1);
            float w  = __shfl_sync(0xffffffffu, wnorm, sidx);

            float x = rx * (float)Ww + ox - 0.5f;
            float y = ry * (float)Hh + oy - 0.5f;
            float x0f = floorf(x), y0f = floorf(y);
            int x0 = (int)x0f, y0 = (int)y0f;
            float wx = x - x0f, wy = y - y0f;
            int x1 = x0 + 1, y1 = y0 + 1;
            bool vx0 = (x0 >= 0) & (x0 < Ww);
            bool vx1 = (x1 >= 0) & (x1 < Ww);
            bool vy0 = (y0 >= 0) & (y0 < Hh);
            bool vy1 = (y1 >= 0) & (y1 < Hh);

            float2 v00 = make_float2(0.f, 0.f), v01 = v00, v10 = v00, v11 = v00;
            if (vy0) {
                size_t rb = pb + (size_t)y0 * Ww;
                if (vx0) v00 = __half22float2(*(const __half2*)&g_valueH[(rb + x0) * 32 + li * 2]);
                if (vx1) v01 = __half22float2(*(const __half2*)&g_valueH[(rb + x1) * 32 + li * 2]);
            }
            if (vy1) {
                size_t rb = pb + (size_t)y1 * Ww;
                if (vx0) v10 = __half22float2(*(const __half2*)&g_valueH[(rb + x0) * 32 + li * 2]);
                if (vx1) v11 = __half22float2(*(const __half2*)&g_valueH[(rb + x1) * 32 + li * 2]);
            }
            float tx0 = v00.x + (v01.x - v00.x) * wx;
            float tx1 = v10.x + (v11.x - v10.x) * wx;
            float ty0 = v00.y + (v01.y - v00.y) * wx;
            float ty1 = v10.y + (v11.y - v10.y) * wx;
            acc.x += w * (tx0 + (tx1 - tx0) * wy);
            acc.y += w * (ty0 + (ty1 - ty0) * wy);
        }
    }
    // combine the two half-warps (points p and p+1)
    acc.x += __shfl_xor_sync(0xffffffffu, acc.x, 16);
    acc.y += __shfl_xor_sync(0xffffffffu, acc.y, 16);
    if (lane < 16) {
        __half2 hv = __floats2half2_rn(acc.x, acc.y);
        *(__half2*)&g_sampH[(size_t)tok * D_MODEL + h * HDIM + li * 2] = hv;
    }
}

// ================= launch =================
extern "C" void kernel_launch(void* const* d_in, const int* in_sizes, int n_in,
                              void* d_out, int out_size) {
    const float* src  = (const float*)d_in[0];
    const float* pos  = (const float*)d_in[1];
    const float* refp = (const float*)d_in[2];
    const float* n1g = (const float*)d_in[5];
    const float* n1b = (const float*)d_in[6];
    const float* n2g = (const float*)d_in[7];
    const float* n2b = (const float*)d_in[8];
    const float* Wv  = (const float*)d_in[9];
    const float* bv  = (const float*)d_in[10];
    const float* Wo  = (const float*)d_in[11];
    const float* bo  = (const float*)d_in[12];
    const float* Wa  = (const float*)d_in[13];
    const float* ba  = (const float*)d_in[14];
    const float* Wout= (const float*)d_in[15];
    const float* bout= (const float*)d_in[16];
    const float* Wf1 = (const float*)d_in[17];
    const float* bf1 = (const float*)d_in[18];
    const float* Wf2 = (const float*)d_in[19];
    const float* bf2 = (const float*)d_in[20];
    float* out = (float*)d_out;

    __half *srcH, *qH, *sampH, *h2H, *ffnH, *valH;
    __half *wv, *wqa, *wo, *wf1, *wf2;
    float *pOff, *pAttn, *pSrc2;
    cudaGetSymbolAddress((void**)&srcH, g_srcH);
    cudaGetSymbolAddress((void**)&qH,   g_qH);
    cudaGetSymbolAddress((void**)&sampH,g_sampH);
    cudaGetSymbolAddress((void**)&h2H,  g_h2H);
    cudaGetSymbolAddress((void**)&ffnH, g_ffnH);
    cudaGetSymbolAddress((void**)&valH, g_valueH);
    cudaGetSymbolAddress((void**)&wv,   w_v);
    cudaGetSymbolAddress((void**)&wqa,  w_qa);
    cudaGetSymbolAddress((void**)&wo,   w_o);
    cudaGetSymbolAddress((void**)&wf1,  w_f1);
    cudaGetSymbolAddress((void**)&wf2,  w_f2);
    cudaGetSymbolAddress((void**)&pOff,  g_off);
    cudaGetSymbolAddress((void**)&pAttn, g_attn);
    cudaGetSymbolAddress((void**)&pSrc2, g_src2);

    cudaFuncSetAttribute(mma_gemm<1>, cudaFuncAttributeMaxDynamicSharedMemorySize, GEMM_SMEM);
    cudaFuncSetAttribute(mma_gemm<2>, cudaFuncAttributeMaxDynamicSharedMemorySize, GEMM_SMEM);
    cudaFuncSetAttribute(mma_gemm<3>, cudaFuncAttributeMaxDynamicSharedMemorySize, GEMM_SMEM);
    cudaFuncSetAttribute(mma_gemm<4>, cudaFuncAttributeMaxDynamicSharedMemorySize, GEMM_SMEM);

    dim3 t256(256), t128(128);
    const int MB = NTOK / 128;   // 340

    pre_kernel<<<NTOK, t256>>>(src, n1g, n1b, pos,                                  // 0 (incl. wprep)
                               Wv, Wo, Wa, Wout, Wf1, Wf2);
    mma_gemm<4><<<dim3(2, MB), t128, GEMM_SMEM>>>(srcH, wv, bv, nullptr,            // 1: value (planar)
                                                  nullptr, nullptr, valH, 256, 256);
    mma_gemm<3><<<dim3(3, MB), t128, GEMM_SMEM>>>(qH, wqa, bo, ba,                  // 2: offsets+logits
                                                  pOff, pAttn, nullptr, 384, 256);
    deform_kernel<<<(NTOK * NHEADS) / 8, t256>>>(refp);                             // 3 <- profiled
    mma_gemm<2><<<dim3(2, MB), t128, GEMM_SMEM>>>(sampH, wo, bout, src,             // 4: out-proj + res
                                                  pSrc2, nullptr, nullptr, 256, 256);
    ln2_kernel<<<NTOK, t256>>>(pSrc2, n2g, n2b);                                    // 5
    mma_gemm<1><<<dim3(8, MB), t128, GEMM_SMEM>>>(h2H, wf1, bf1, nullptr,           // 6: FFN1 + gelu
                                                  nullptr, nullptr, ffnH, 1024, 256);
    mma_gemm<2><<<dim3(2, MB), t128, GEMM_SMEM>>>(ffnH, wf2, bf2, pSrc2,            // 7: FFN2 + res
                                                  out, nullptr, nullptr, 256, 1024);
}

// round 11
// speedup vs baseline: 1.3428x; 1.1680x over previous
#include <cuda_runtime.h>
#include <cuda_fp16.h>
#include <math.h>
#include <stdint.h>

#define D_MODEL 256
#define D_FFN   1024
#define NHEADS  8
#define NLEV    4
#define NPTS    4
#define HDIM    32
#define BATCH   2
#define SLEN    21760
#define NTOK    (BATCH * SLEN)   // 43520

// ================= scratch (device globals; no allocation allowed) =================
__device__ __align__(16) __half g_srcH[NTOK * D_MODEL];
__device__ __align__(16) __half g_qH[NTOK * D_MODEL];
__device__ __align__(16) __half g_sampH[NTOK * D_MODEL];
__device__ __align__(16) __half g_h2H[NTOK * D_MODEL];
__device__ __align__(16) __half g_ffnH[NTOK * D_FFN];
__device__ __align__(16) __half g_valueH[NTOK * D_MODEL];     // planar: [h][tok][dim]

__device__ float g_off[NTOK * D_MODEL];
__device__ float g_attn[NTOK * NHEADS * 16];                  // raw logits
__device__ float g_src2[NTOK * D_MODEL];

// weights transposed [N][K], fp16
__device__ __align__(16) __half w_v[256 * 256];
__device__ __align__(16) __half w_qa[384 * 256];              // 0-255: W_off, 256-383: W_attn
__device__ __align__(16) __half w_o[256 * 256];
__device__ __align__(16) __half w_f1[1024 * 256];
__device__ __align__(16) __half w_f2[256 * 1024];

// ================= helpers =================
__device__ __forceinline__ uint32_t smem_u32(const void* p) {
    uint32_t a;
    asm("{ .reg .u64 t; cvta.to.shared.u64 t, %1; cvt.u32.u64 %0, t; }" : "=r"(a) : "l"(p));
    return a;
}
__device__ __forceinline__ void ldm_x4(uint32_t* r, uint32_t addr) {
    asm volatile("ldmatrix.sync.aligned.m8n8.x4.shared.b16 {%0,%1,%2,%3}, [%4];"
                 : "=r"(r[0]), "=r"(r[1]), "=r"(r[2]), "=r"(r[3]) : "r"(addr));
}
__device__ __forceinline__ void mma16816(float* d, const uint32_t* a, const uint32_t* b) {
    asm volatile("mma.sync.aligned.m16n8k16.row.col.f32.f16.f16.f32 "
                 "{%0,%1,%2,%3}, {%4,%5,%6,%7}, {%8,%9}, {%0,%1,%2,%3};"
                 : "+f"(d[0]), "+f"(d[1]), "+f"(d[2]), "+f"(d[3])
                 : "r"(a[0]), "r"(a[1]), "r"(a[2]), "r"(a[3]), "r"(b[0]), "r"(b[1]));
}
__device__ __forceinline__ void cpa16(uint32_t dst, const void* src) {
    asm volatile("cp.async.cg.shared.global [%0], [%1], 16;" :: "r"(dst), "l"(src));
}

// ================= fp16 HMMA GEMM (R6 config): CTA 128x128, 4 warps of 64x64 =================
// 128 threads, BK=64, 3-stage cp.async ring, 2 CTAs/SM.
// EPI: 1 = gelu(x+bias) -> fp16; 2 = x+bias+aux(residual) -> fp32;
//      3 = dual (N=384): col<256 -> C(bias), col>=256 -> Cb(aux bias);
//      4 = fp16 planar value: Ch[((col>>5)*NTOK+row)*32 + (col&31)]
static const int LDSB = 144;                  // 64 fp16 (128 B) + 16 B pad
static const int BUFB = 128 * LDSB;           // 18432 B
static const int GEMM_SMEM = 6 * BUFB;        // 110592 B

template <int EPI>
__global__ void __launch_bounds__(128, 2) mma_gemm(
    const __half* __restrict__ A, const __half* __restrict__ B,
    const float* __restrict__ bias, const float* __restrict__ aux,
    float* __restrict__ C, float* __restrict__ Cb, __half* __restrict__ Ch,
    int N, int K)
{
    extern __shared__ __align__(16) char sm[];
    const uint32_t smb = smem_u32(sm);
    const int tid = threadIdx.x;
    const int wid = tid >> 5, lane = tid & 31;
    const int wm = wid >> 1, wn = wid & 1;                // 2x2 warps of 64x64
    const int m0 = blockIdx.y * 128, n0 = blockIdx.x * 128;
    const int S = K >> 6;

    float acc[4][8][4];
    #pragma unroll
    for (int i = 0; i < 4; i++)
        #pragma unroll
        for (int j = 0; j < 8; j++)
            #pragma unroll
            for (int r = 0; r < 4; r++) acc[i][j][r] = 0.f;

    auto prefetch = [&](int s) {
        int k0 = s << 6;
        const uint32_t ab = smb + (uint32_t)(s % 3) * (2u * BUFB);
        const uint32_t bb = ab + BUFB;
        #pragma unroll
        for (int i = 0; i < 16; i++) {
            int c = tid + (i << 7);                       // 0..2047
            int cc = c & 1023;
            int row = cc >> 3;
            int kc  = (cc & 7) << 3;
            uint32_t dst; const __half* src;
            if (c < 1024) {
                dst = ab + (uint32_t)(row * LDSB + kc * 2);
                src = A + (size_t)(m0 + row) * K + k0 + kc;
            } else {
                dst = bb + (uint32_t)(row * LDSB + kc * 2);
                src = B + (size_t)(n0 + row) * K + k0 + kc;
            }
            cpa16(dst, src);
        }
        asm volatile("cp.async.commit_group;");
    };

    prefetch(0);
    if (S > 1) prefetch(1);

    for (int s = 0; s < S; s++) {
        if (s + 1 < S) asm volatile("cp.async.wait_group 1;");
        else           asm volatile("cp.async.wait_group 0;");
        __syncthreads();
        if (s + 2 < S) prefetch(s + 2);

        const uint32_t ab = smb + (uint32_t)(s % 3) * (2u * BUFB);
        const uint32_t bb = ab + BUFB;
        const uint32_t aoff = ab + (uint32_t)(((lane & 15) + wm * 64) * LDSB + ((lane >> 4) << 4));
        const uint32_t boff = bb + (uint32_t)((((lane & 7) + ((lane >> 4) << 3)) + wn * 64) * LDSB
                                              + (((lane >> 3) & 1) << 4));
        #pragma unroll
        for (int ks = 0; ks < 4; ks++) {
            const uint32_t kb = (uint32_t)(ks << 5);
            uint32_t afr[4][4], bfr[8][2];
            #pragma unroll
            for (int mi = 0; mi < 4; mi++)
                ldm_x4(afr[mi], aoff + (uint32_t)(mi * 16 * LDSB) + kb);
            #pragma unroll
            for (int nj = 0; nj < 4; nj++) {
                uint32_t r[4];
                ldm_x4(r, boff + (uint32_t)(nj * 16 * LDSB) + kb);
                bfr[nj * 2][0] = r[0]; bfr[nj * 2][1] = r[1];
                bfr[nj * 2 + 1][0] = r[2]; bfr[nj * 2 + 1][1] = r[3];
            }
            #pragma unroll
            for (int mi = 0; mi < 4; mi++)
                #pragma unroll
                for (int ni = 0; ni < 8; ni++)
                    mma16816(acc[mi][ni], afr[mi], bfr[ni]);
        }
    }
    __syncthreads();

    // ---- epilogue: stage 64x64 per warp in smem (stride 68 floats), store coalesced ----
    float* ws = (float*)sm + wid * (64 * 68);
    const int er = lane >> 2, ec = (lane & 3) * 2;
    #pragma unroll
    for (int mi = 0; mi < 4; mi++)
        #pragma unroll
        for (int ni = 0; ni < 8; ni++) {
            *(float2*)&ws[(mi * 16 + er) * 68 + ni * 8 + ec]     = make_float2(acc[mi][ni][0], acc[mi][ni][1]);
            *(float2*)&ws[(mi * 16 + er + 8) * 68 + ni * 8 + ec] = make_float2(acc[mi][ni][2], acc[mi][ni][3]);
        }
    __syncwarp();

    const int gc0 = n0 + wn * 64 + lane;
    const int gc1 = gc0 + 32;
    float b0, b1;
    if (EPI == 3) {
        b0 = (gc0 < 256) ? bias[gc0] : aux[gc0 - 256];
        b1 = (gc1 < 256) ? bias[gc1] : aux[gc1 - 256];
    } else { b0 = bias[gc0]; b1 = bias[gc1]; }

    for (int r = 0; r < 64; r++) {
        const int gr = m0 + wm * 64 + r;
        float v0 = ws[r * 68 + lane] + b0;
        float v1 = ws[r * 68 + 32 + lane] + b1;
        if (EPI == 1) {
            v0 = 0.5f * v0 * (1.0f + erff(v0 * 0.70710678118654752f));
            v1 = 0.5f * v1 * (1.0f + erff(v1 * 0.70710678118654752f));
            Ch[(size_t)gr * N + gc0] = __float2half(v0);
            Ch[(size_t)gr * N + gc1] = __float2half(v1);
        } else if (EPI == 2) {
            C[(size_t)gr * N + gc0] = v0 + aux[(size_t)gr * N + gc0];
            C[(size_t)gr * N + gc1] = v1 + aux[(size_t)gr * N + gc1];
        } else if (EPI == 3) {
            if (gc0 < 256) C[(size_t)gr * 256 + gc0] = v0;
            else           Cb[(size_t)gr * 128 + (gc0 - 256)] = v0;
            if (gc1 < 256) C[(size_t)gr * 256 + gc1] = v1;
            else           Cb[(size_t)gr * 128 + (gc1 - 256)] = v1;
        } else {  // EPI == 4: planar value
            Ch[((size_t)(gc0 >> 5) * NTOK + gr) * 32 + (gc0 & 31)] = __float2half(v0);
            Ch[((size_t)(gc1 >> 5) * NTOK + gr) * 32 + (gc1 & 31)] = __float2half(v1);
        }
    }
}

// ================= fused prep: src->fp16, q=LN1(src)+pos->fp16, AND weight prep =================
__global__ void pre_kernel(const float* __restrict__ x,
                           const float* __restrict__ gamma,
                           const float* __restrict__ beta,
                           const float* __restrict__ pos,
                           const float* __restrict__ Wv, const float* __restrict__ Wo,
                           const float* __restrict__ Wa, const float* __restrict__ Wout,
                           const float* __restrict__ Wf1, const float* __restrict__ Wf2) {
    int t = blockIdx.x;
    int c = threadIdx.x;

    // ---- weight prep slice (first 2944 blocks; 753664 = 2944*256) ----
    int i = t * 256 + c;
    if (i < 753664) {
        const float* W; __half* B; int K, N, rowOff, i2;
        if (i < 65536)        { W = Wv;  B = w_v;  K = 256;  N = 256;  rowOff = 0;   i2 = i; }
        else if (i < 131072)  { W = Wo;  B = w_qa; K = 256;  N = 256;  rowOff = 0;   i2 = i - 65536; }
        else if (i < 163840)  { W = Wa;  B = w_qa; K = 256;  N = 128;  rowOff = 256; i2 = i - 131072; }
        else if (i < 229376)  { W = Wout;B = w_o;  K = 256;  N = 256;  rowOff = 0;   i2 = i - 163840; }
        else if (i < 491520)  { W = Wf1; B = w_f1; K = 256;  N = 1024; rowOff = 0;   i2 = i - 229376; }
        else                  { W = Wf2; B = w_f2; K = 1024; N = 256;  rowOff = 0;   i2 = i - 491520; }
        int k = i2 / N, n = i2 - k * N;
        B[(size_t)(n + rowOff) * K + k] = __float2half(W[i2]);
    }

    // ---- per-token prep ----
    float v = x[t * D_MODEL + c];
    g_srcH[(size_t)t * D_MODEL + c] = __float2half(v);
    float a = v, a2 = v * v;
    #pragma unroll
    for (int o = 16; o; o >>= 1) {
        a  += __shfl_xor_sync(0xffffffffu, a,  o);
        a2 += __shfl_xor_sync(0xffffffffu, a2, o);
    }
    __shared__ float s1[8], s2[8];
    if ((c & 31) == 0) { s1[c >> 5] = a; s2[c >> 5] = a2; }
    __syncthreads();
    float sum = 0.f, sq = 0.f;
    #pragma unroll
    for (int j = 0; j < 8; j++) { sum += s1[j]; sq += s2[j]; }
    float mu  = sum * (1.0f / D_MODEL);
    float var = sq * (1.0f / D_MODEL) - mu * mu;
    float rr  = rsqrtf(var + 1e-5f);
    float y   = (v - mu) * rr * gamma[c] + beta[c] + pos[t * D_MODEL + c];
    g_qH[(size_t)t * D_MODEL + c] = __float2half(y);
}

// ================= layernorm2 -> fp16 =================
__global__ void ln2_kernel(const float* __restrict__ x,
                           const float* __restrict__ gamma,
                           const float* __restrict__ beta) {
    int t = blockIdx.x;
    int c = threadIdx.x;
    float v = x[t * D_MODEL + c];
    float a = v, a2 = v * v;
    #pragma unroll
    for (int o = 16; o; o >>= 1) {
        a  += __shfl_xor_sync(0xffffffffu, a,  o);
        a2 += __shfl_xor_sync(0xffffffffu, a2, o);
    }
    __shared__ float s1[8], s2[8];
    if ((c & 31) == 0) { s1[c >> 5] = a; s2[c >> 5] = a2; }
    __syncthreads();
    float sum = 0.f, sq = 0.f;
    #pragma unroll
    for (int i = 0; i < 8; i++) { sum += s1[i]; sq += s2[i]; }
    float mu  = sum * (1.0f / D_MODEL);
    float var = sq * (1.0f / D_MODEL) - mu * mu;
    float rr  = rsqrtf(var + 1e-5f);
    float y   = (v - mu) * rr * gamma[c] + beta[c];
    g_h2H[(size_t)t * D_MODEL + c] = __float2half(y);
}

// ================= deform v4: per-lane point precompute + branchless clamp, 32-bit indexing =================
// One warp per (tok, h). Precompute: lane sidx (0..15) computes its point's clamped
// corner indices + validity-zeroed weights. Main loop: 8 iters (point pair via half),
// shfl-distributed, 4 unconditional LDG per lane per iter.
__global__ void deform_kernel(const float* __restrict__ ref) {
    const int lvH[4] = {128, 64, 32, 16};
    const int lvW[4] = {128, 64, 32, 16};
    const int lvS[4] = {0, 16384, 20480, 21504};

    int g = blockIdx.x * 8 + (threadIdx.x >> 5);
    int lane = threadIdx.x & 31;
    int b  = g / (SLEN * NHEADS);
    int rm = g - b * (SLEN * NHEADS);
    int qi = rm / NHEADS;
    int h  = rm - qi * NHEADS;
    int tok = b * SLEN + qi;

    // --- scalar prefetch: 32 offsets, 8 ref floats, 16 logits ---
    float offv = g_off[(size_t)tok * 256 + h * 32 + lane];
    float refv = (lane < 8) ? ref[(size_t)tok * 8 + lane] : 0.f;
    float lg   = (lane < 16) ? g_attn[(size_t)tok * 128 + h * 16 + lane] : -1e30f;

    // softmax over 16 logits
    float mx = lg;
    #pragma unroll
    for (int o = 8; o; o >>= 1) mx = fmaxf(mx, __shfl_xor_sync(0xffffffffu, mx, o));
    float e = (lane < 16) ? __expf(lg - mx) : 0.f;
    float se = e;
    #pragma unroll
    for (int o = 8; o; o >>= 1) se += __shfl_xor_sync(0xffffffffu, se, o);
    float wnorm = e / se;

    // --- precompute: lane sidx owns point sidx (lanes 16-31 mirror 0-15) ---
    uint32_t c00, c01, c10, c11;
    float w00, w01, w10, w11;
    {
        const int sidx = lane & 15;
        const int lvl  = sidx >> 2;
        const int Ww = lvW[lvl], Hh = lvH[lvl];
        float rx = __shfl_sync(0xffffffffu, refv, lvl * 2 + 0);
        float ry = __shfl_sync(0xffffffffu, refv, lvl * 2 + 1);
        float ox = __shfl_sync(0xffffffffu, offv, sidx * 2 + 0);
        float oy = __shfl_sync(0xffffffffu, offv, sidx * 2 + 1);
        float w  = __shfl_sync(0xffffffffu, wnorm, sidx);

        float x = fmaf(rx, (float)Ww, ox) - 0.5f;
        float y = fmaf(ry, (float)Hh, oy) - 0.5f;
        float x0f = floorf(x), y0f = floorf(y);
        int x0 = (int)x0f, y0 = (int)y0f;
        float wx = x - x0f, wy = y - y0f;
        int x1 = x0 + 1, y1 = y0 + 1;

        float vx0 = ((unsigned)x0 < (unsigned)Ww) ? 1.f : 0.f;
        float vx1 = ((unsigned)x1 < (unsigned)Ww) ? 1.f : 0.f;
        float vy0 = ((unsigned)y0 < (unsigned)Hh) ? 1.f : 0.f;
        float vy1 = ((unsigned)y1 < (unsigned)Hh) ? 1.f : 0.f;

        int x0c = min(max(x0, 0), Ww - 1), x1c = min(max(x1, 0), Ww - 1);
        int y0c = min(max(y0, 0), Hh - 1), y1c = min(max(y1, 0), Hh - 1);

        uint32_t pb = (uint32_t)h * NTOK + (uint32_t)(b * SLEN + lvS[lvl]);
        uint32_t r0 = pb + (uint32_t)(y0c * Ww), r1 = pb + (uint32_t)(y1c * Ww);
        c00 = r0 + (uint32_t)x0c; c01 = r0 + (uint32_t)x1c;
        c10 = r1 + (uint32_t)x0c; c11 = r1 + (uint32_t)x1c;

        float wx0 = 1.f - wx, wy0 = 1.f - wy;
        w00 = w * wx0 * wy0 * (vx0 * vy0);
        w01 = w * wx  * wy0 * (vx1 * vy0);
        w10 = w * wx0 * wy  * (vx0 * vy1);
        w11 = w * wx  * wy  * (vx1 * vy1);
    }

    // --- main loop: lane handles point 2*it+half, all 4 corners of its dim pair ---
    const int half = lane >> 4;
    const uint32_t li = (uint32_t)(lane & 15);
    const __half2* vbase = (const __half2*)g_valueH;
    float2 acc = make_float2(0.f, 0.f);
    #pragma unroll
    for (int it = 0; it < 8; it++) {
        const int sp = it * 2 + half;
        uint32_t a00 = __shfl_sync(0xffffffffu, c00, sp) * 16u + li;
        uint32_t a01 = __shfl_sync(0xffffffffu, c01, sp) * 16u + li;
        uint32_t a10 = __shfl_sync(0xffffffffu, c10, sp) * 16u + li;
        uint32_t a11 = __shfl_sync(0xffffffffu, c11, sp) * 16u + li;
        float u00 = __shfl_sync(0xffffffffu, w00, sp);
        float u01 = __shfl_sync(0xffffffffu, w01, sp);
        float u10 = __shfl_sync(0xffffffffu, w10, sp);
        float u11 = __shfl_sync(0xffffffffu, w11, sp);
        float2 v00 = __half22float2(vbase[a00]);
        float2 v01 = __half22float2(vbase[a01]);
        float2 v10 = __half22float2(vbase[a10]);
        float2 v11 = __half22float2(vbase[a11]);
        acc.x += v00.x * u00 + v01.x * u01 + v10.x * u10 + v11.x * u11;
        acc.y += v00.y * u00 + v01.y * u01 + v10.y * u10 + v11.y * u11;
    }
    // combine the two half-warps (each covered half the points)
    acc.x += __shfl_xor_sync(0xffffffffu, acc.x, 16);
    acc.y += __shfl_xor_sync(0xffffffffu, acc.y, 16);
    if (lane < 16) {
        __half2 hv = __floats2half2_rn(acc.x, acc.y);
        *(__half2*)&g_sampH[(size_t)tok * D_MODEL + h * HDIM + li * 2] = hv;
    }
}

// ================= launch =================
extern "C" void kernel_launch(void* const* d_in, const int* in_sizes, int n_in,
                              void* d_out, int out_size) {
    const float* src  = (const float*)d_in[0];
    const float* pos  = (const float*)d_in[1];
    const float* refp = (const float*)d_in[2];
    const float* n1g = (const float*)d_in[5];
    const float* n1b = (const float*)d_in[6];
    const float* n2g = (const float*)d_in[7];
    const float* n2b = (const float*)d_in[8];
    const float* Wv  = (const float*)d_in[9];
    const float* bv  = (const float*)d_in[10];
    const float* Wo  = (const float*)d_in[11];
    const float* bo  = (const float*)d_in[12];
    const float* Wa  = (const float*)d_in[13];
    const float* ba  = (const float*)d_in[14];
    const float* Wout= (const float*)d_in[15];
    const float* bout= (const float*)d_in[16];
    const float* Wf1 = (const float*)d_in[17];
    const float* bf1 = (const float*)d_in[18];
    const float* Wf2 = (const float*)d_in[19];
    const float* bf2 = (const float*)d_in[20];
    float* out = (float*)d_out;

    __half *srcH, *qH, *sampH, *h2H, *ffnH, *valH;
    __half *wv, *wqa, *wo, *wf1, *wf2;
    float *pOff, *pAttn, *pSrc2;
    cudaGetSymbolAddress((void**)&srcH, g_srcH);
    cudaGetSymbolAddress((void**)&qH,   g_qH);
    cudaGetSymbolAddress((void**)&sampH,g_sampH);
    cudaGetSymbolAddress((void**)&h2H,  g_h2H);
    cudaGetSymbolAddress((void**)&ffnH, g_ffnH);
    cudaGetSymbolAddress((void**)&valH, g_valueH);
    cudaGetSymbolAddress((void**)&wv,   w_v);
    cudaGetSymbolAddress((void**)&wqa,  w_qa);
    cudaGetSymbolAddress((void**)&wo,   w_o);
    cudaGetSymbolAddress((void**)&wf1,  w_f1);
    cudaGetSymbolAddress((void**)&wf2,  w_f2);
    cudaGetSymbolAddress((void**)&pOff,  g_off);
    cudaGetSymbolAddress((void**)&pAttn, g_attn);
    cudaGetSymbolAddress((void**)&pSrc2, g_src2);

    cudaFuncSetAttribute(mma_gemm<1>, cudaFuncAttributeMaxDynamicSharedMemorySize, GEMM_SMEM);
    cudaFuncSetAttribute(mma_gemm<2>, cudaFuncAttributeMaxDynamicSharedMemorySize, GEMM_SMEM);
    cudaFuncSetAttribute(mma_gemm<3>, cudaFuncAttributeMaxDynamicSharedMemorySize, GEMM_SMEM);
    cudaFuncSetAttribute(mma_gemm<4>, cudaFuncAttributeMaxDynamicSharedMemorySize, GEMM_SMEM);

    dim3 t256(256), t128(128);
    const int MB = NTOK / 128;   // 340

    pre_kernel<<<NTOK, t256>>>(src, n1g, n1b, pos,                                  // 0 (incl. wprep)
                               Wv, Wo, Wa, Wout, Wf1, Wf2);
    mma_gemm<4><<<dim3(2, MB), t128, GEMM_SMEM>>>(srcH, wv, bv, nullptr,            // 1: value (planar)
                                                  nullptr, nullptr, valH, 256, 256);
    mma_gemm<3><<<dim3(3, MB), t128, GEMM_SMEM>>>(qH, wqa, bo, ba,                  // 2: offsets+logits
                                                  pOff, pAttn, nullptr, 384, 256);
    deform_kernel<<<(NTOK * NHEADS) / 8, t256>>>(refp);                             // 3 <- profiled
    mma_gemm<2><<<dim3(2, MB), t128, GEMM_SMEM>>>(sampH, wo, bout, src,             // 4: out-proj + res
                                                  pSrc2, nullptr, nullptr, 256, 256);
    ln2_kernel<<<NTOK, t256>>>(pSrc2, n2g, n2b);                                    // 5
    mma_gemm<1><<<dim3(8, MB), t128, GEMM_SMEM>>>(h2H, wf1, bf1, nullptr,           // 6: FFN1 + gelu
                                                  nullptr, nullptr, ffnH, 1024, 256);
    mma_gemm<2><<<dim3(2, MB), t128, GEMM_SMEM>>>(ffnH, wf2, bf2, pSrc2,            // 7: FFN2 + res
                                                  out, nullptr, nullptr, 256, 1024);
}

// round 12
// speedup vs baseline: 1.4455x; 1.0765x over previous
#include <cuda_runtime.h>
#include <cuda_fp16.h>
#include <math.h>
#include <stdint.h>

#define D_MODEL 256
#define D_FFN   1024
#define NHEADS  8
#define NLEV    4
#define NPTS    4
#define HDIM    32
#define BATCH   2
#define SLEN    21760
#define NTOK    (BATCH * SLEN)   // 43520

// ================= scratch (device globals; no allocation allowed) =================
__device__ __align__(16) __half g_srcH[NTOK * D_MODEL];
__device__ __align__(16) __half g_qH[NTOK * D_MODEL];
__device__ __align__(16) __half g_sampH[NTOK * D_MODEL];
__device__ __align__(16) __half g_h2H[NTOK * D_MODEL];
__device__ __align__(16) __half g_ffnH[NTOK * D_FFN];
__device__ __align__(16) __half g_valueH[NTOK * D_MODEL];     // planar: [h][tok][dim]

__device__ float g_off[NTOK * D_MODEL];
__device__ float g_attn[NTOK * NHEADS * 16];                  // raw logits
__device__ float g_src2[NTOK * D_MODEL];

// weights transposed [N][K], fp16
__device__ __align__(16) __half w_v[256 * 256];
__device__ __align__(16) __half w_qa[384 * 256];              // 0-255: W_off, 256-383: W_attn
__device__ __align__(16) __half w_o[256 * 256];
__device__ __align__(16) __half w_f1[1024 * 256];
__device__ __align__(16) __half w_f2[256 * 1024];

// ================= helpers =================
__device__ __forceinline__ uint32_t smem_u32(const void* p) {
    uint32_t a;
    asm("{ .reg .u64 t; cvta.to.shared.u64 t, %1; cvt.u32.u64 %0, t; }" : "=r"(a) : "l"(p));
    return a;
}
__device__ __forceinline__ void ldm_x4(uint32_t* r, uint32_t addr) {
    asm volatile("ldmatrix.sync.aligned.m8n8.x4.shared.b16 {%0,%1,%2,%3}, [%4];"
                 : "=r"(r[0]), "=r"(r[1]), "=r"(r[2]), "=r"(r[3]) : "r"(addr));
}
__device__ __forceinline__ void mma16816(float* d, const uint32_t* a, const uint32_t* b) {
    asm volatile("mma.sync.aligned.m16n8k16.row.col.f32.f16.f16.f32 "
                 "{%0,%1,%2,%3}, {%4,%5,%6,%7}, {%8,%9}, {%0,%1,%2,%3};"
                 : "+f"(d[0]), "+f"(d[1]), "+f"(d[2]), "+f"(d[3])
                 : "r"(a[0]), "r"(a[1]), "r"(a[2]), "r"(a[3]), "r"(b[0]), "r"(b[1]));
}
__device__ __forceinline__ void cpa16(uint32_t dst, const void* src) {
    asm volatile("cp.async.cg.shared.global [%0], [%1], 16;" :: "r"(dst), "l"(src));
}

// ================= fp16 HMMA GEMM (R6 config): CTA 128x128, 4 warps of 64x64 =================
// 128 threads, BK=64, 3-stage cp.async ring, 2 CTAs/SM.
// EPI: 1 = gelu(x+bias) -> fp16; 2 = x+bias+aux(residual) -> fp32;
//      3 = dual (N=384): col<256 -> C(bias), col>=256 -> Cb(aux bias);
//      4 = fp16 planar value: Ch[((col>>5)*NTOK+row)*32 + (col&31)]
static const int LDSB = 144;                  // 64 fp16 (128 B) + 16 B pad
static const int BUFB = 128 * LDSB;           // 18432 B
static const int GEMM_SMEM = 6 * BUFB;        // 110592 B

template <int EPI>
__global__ void __launch_bounds__(128, 2) mma_gemm(
    const __half* __restrict__ A, const __half* __restrict__ B,
    const float* __restrict__ bias, const float* __restrict__ aux,
    float* __restrict__ C, float* __restrict__ Cb, __half* __restrict__ Ch,
    int N, int K)
{
    extern __shared__ __align__(16) char sm[];
    const uint32_t smb = smem_u32(sm);
    const int tid = threadIdx.x;
    const int wid = tid >> 5, lane = tid & 31;
    const int wm = wid >> 1, wn = wid & 1;                // 2x2 warps of 64x64
    const int m0 = blockIdx.y * 128, n0 = blockIdx.x * 128;
    const int S = K >> 6;

    float acc[4][8][4];
    #pragma unroll
    for (int i = 0; i < 4; i++)
        #pragma unroll
        for (int j = 0; j < 8; j++)
            #pragma unroll
            for (int r = 0; r < 4; r++) acc[i][j][r] = 0.f;

    auto prefetch = [&](int s) {
        int k0 = s << 6;
        const uint32_t ab = smb + (uint32_t)(s % 3) * (2u * BUFB);
        const uint32_t bb = ab + BUFB;
        #pragma unroll
        for (int i = 0; i < 16; i++) {
            int c = tid + (i << 7);                       // 0..2047
            int cc = c & 1023;
            int row = cc >> 3;
            int kc  = (cc & 7) << 3;
            uint32_t dst; const __half* src;
            if (c < 1024) {
                dst = ab + (uint32_t)(row * LDSB + kc * 2);
                src = A + (size_t)(m0 + row) * K + k0 + kc;
            } else {
                dst = bb + (uint32_t)(row * LDSB + kc * 2);
                src = B + (size_t)(n0 + row) * K + k0 + kc;
            }
            cpa16(dst, src);
        }
        asm volatile("cp.async.commit_group;");
    };

    prefetch(0);
    if (S > 1) prefetch(1);

    for (int s = 0; s < S; s++) {
        if (s + 1 < S) asm volatile("cp.async.wait_group 1;");
        else           asm volatile("cp.async.wait_group 0;");
        __syncthreads();
        if (s + 2 < S) prefetch(s + 2);

        const uint32_t ab = smb + (uint32_t)(s % 3) * (2u * BUFB);
        const uint32_t bb = ab + BUFB;
        const uint32_t aoff = ab + (uint32_t)(((lane & 15) + wm * 64) * LDSB + ((lane >> 4) << 4));
        const uint32_t boff = bb + (uint32_t)((((lane & 7) + ((lane >> 4) << 3)) + wn * 64) * LDSB
                                              + (((lane >> 3) & 1) << 4));
        #pragma unroll
        for (int ks = 0; ks < 4; ks++) {
            const uint32_t kb = (uint32_t)(ks << 5);
            uint32_t afr[4][4], bfr[8][2];
            #pragma unroll
            for (int mi = 0; mi < 4; mi++)
                ldm_x4(afr[mi], aoff + (uint32_t)(mi * 16 * LDSB) + kb);
            #pragma unroll
            for (int nj = 0; nj < 4; nj++) {
                uint32_t r[4];
                ldm_x4(r, boff + (uint32_t)(nj * 16 * LDSB) + kb);
                bfr[nj * 2][0] = r[0]; bfr[nj * 2][1] = r[1];
                bfr[nj * 2 + 1][0] = r[2]; bfr[nj * 2 + 1][1] = r[3];
            }
            #pragma unroll
            for (int mi = 0; mi < 4; mi++)
                #pragma unroll
                for (int ni = 0; ni < 8; ni++)
                    mma16816(acc[mi][ni], afr[mi], bfr[ni]);
        }
    }
    __syncthreads();

    // ---- epilogue: stage 64x64 per warp in smem (stride 68 floats), store coalesced ----
    float* ws = (float*)sm + wid * (64 * 68);
    const int er = lane >> 2, ec = (lane & 3) * 2;
    #pragma unroll
    for (int mi = 0; mi < 4; mi++)
        #pragma unroll
        for (int ni = 0; ni < 8; ni++) {
            *(float2*)&ws[(mi * 16 + er) * 68 + ni * 8 + ec]     = make_float2(acc[mi][ni][0], acc[mi][ni][1]);
            *(float2*)&ws[(mi * 16 + er + 8) * 68 + ni * 8 + ec] = make_float2(acc[mi][ni][2], acc[mi][ni][3]);
        }
    __syncwarp();

    const int gc0 = n0 + wn * 64 + lane;
    const int gc1 = gc0 + 32;
    float b0, b1;
    if (EPI == 3) {
        b0 = (gc0 < 256) ? bias[gc0] : aux[gc0 - 256];
        b1 = (gc1 < 256) ? bias[gc1] : aux[gc1 - 256];
    } else { b0 = bias[gc0]; b1 = bias[gc1]; }

    for (int r = 0; r < 64; r++) {
        const int gr = m0 + wm * 64 + r;
        float v0 = ws[r * 68 + lane] + b0;
        float v1 = ws[r * 68 + 32 + lane] + b1;
        if (EPI == 1) {
            v0 = 0.5f * v0 * (1.0f + erff(v0 * 0.70710678118654752f));
            v1 = 0.5f * v1 * (1.0f + erff(v1 * 0.70710678118654752f));
            Ch[(size_t)gr * N + gc0] = __float2half(v0);
            Ch[(size_t)gr * N + gc1] = __float2half(v1);
        } else if (EPI == 2) {
            C[(size_t)gr * N + gc0] = v0 + aux[(size_t)gr * N + gc0];
            C[(size_t)gr * N + gc1] = v1 + aux[(size_t)gr * N + gc1];
        } else if (EPI == 3) {
            if (gc0 < 256) C[(size_t)gr * 256 + gc0] = v0;
            else           Cb[(size_t)gr * 128 + (gc0 - 256)] = v0;
            if (gc1 < 256) C[(size_t)gr * 256 + gc1] = v1;
            else           Cb[(size_t)gr * 128 + (gc1 - 256)] = v1;
        } else {  // EPI == 4: planar value
            Ch[((size_t)(gc0 >> 5) * NTOK + gr) * 32 + (gc0 & 31)] = __float2half(v0);
            Ch[((size_t)(gc1 >> 5) * NTOK + gr) * 32 + (gc1 & 31)] = __float2half(v1);
        }
    }
}

// ================= fused prep: src->fp16, q=LN1(src)+pos->fp16, AND weight prep =================
__global__ void pre_kernel(const float* __restrict__ x,
                           const float* __restrict__ gamma,
                           const float* __restrict__ beta,
                           const float* __restrict__ pos,
                           const float* __restrict__ Wv, const float* __restrict__ Wo,
                           const float* __restrict__ Wa, const float* __restrict__ Wout,
                           const float* __restrict__ Wf1, const float* __restrict__ Wf2) {
    int t = blockIdx.x;
    int c = threadIdx.x;

    // ---- weight prep slice (first 2944 blocks; 753664 = 2944*256) ----
    int i = t * 256 + c;
    if (i < 753664) {
        const float* W; __half* B; int K, N, rowOff, i2;
        if (i < 65536)        { W = Wv;  B = w_v;  K = 256;  N = 256;  rowOff = 0;   i2 = i; }
        else if (i < 131072)  { W = Wo;  B = w_qa; K = 256;  N = 256;  rowOff = 0;   i2 = i - 65536; }
        else if (i < 163840)  { W = Wa;  B = w_qa; K = 256;  N = 128;  rowOff = 256; i2 = i - 131072; }
        else if (i < 229376)  { W = Wout;B = w_o;  K = 256;  N = 256;  rowOff = 0;   i2 = i - 163840; }
        else if (i < 491520)  { W = Wf1; B = w_f1; K = 256;  N = 1024; rowOff = 0;   i2 = i - 229376; }
        else                  { W = Wf2; B = w_f2; K = 1024; N = 256;  rowOff = 0;   i2 = i - 491520; }
        int k = i2 / N, n = i2 - k * N;
        B[(size_t)(n + rowOff) * K + k] = __float2half(W[i2]);
    }

    // ---- per-token prep ----
    float v = x[t * D_MODEL + c];
    g_srcH[(size_t)t * D_MODEL + c] = __float2half(v);
    float a = v, a2 = v * v;
    #pragma unroll
    for (int o = 16; o; o >>= 1) {
        a  += __shfl_xor_sync(0xffffffffu, a,  o);
        a2 += __shfl_xor_sync(0xffffffffu, a2, o);
    }
    __shared__ float s1[8], s2[8];
    if ((c & 31) == 0) { s1[c >> 5] = a; s2[c >> 5] = a2; }
    __syncthreads();
    float sum = 0.f, sq = 0.f;
    #pragma unroll
    for (int j = 0; j < 8; j++) { sum += s1[j]; sq += s2[j]; }
    float mu  = sum * (1.0f / D_MODEL);
    float var = sq * (1.0f / D_MODEL) - mu * mu;
    float rr  = rsqrtf(var + 1e-5f);
    float y   = (v - mu) * rr * gamma[c] + beta[c] + pos[t * D_MODEL + c];
    g_qH[(size_t)t * D_MODEL + c] = __float2half(y);
}

// ================= layernorm2 -> fp16 =================
__global__ void ln2_kernel(const float* __restrict__ x,
                           const float* __restrict__ gamma,
                           const float* __restrict__ beta) {
    int t = blockIdx.x;
    int c = threadIdx.x;
    float v = x[t * D_MODEL + c];
    float a = v, a2 = v * v;
    #pragma unroll
    for (int o = 16; o; o >>= 1) {
        a  += __shfl_xor_sync(0xffffffffu, a,  o);
        a2 += __shfl_xor_sync(0xffffffffu, a2, o);
    }
    __shared__ float s1[8], s2[8];
    if ((c & 31) == 0) { s1[c >> 5] = a; s2[c >> 5] = a2; }
    __syncthreads();
    float sum = 0.f, sq = 0.f;
    #pragma unroll
    for (int i = 0; i < 8; i++) { sum += s1[i]; sq += s2[i]; }
    float mu  = sum * (1.0f / D_MODEL);
    float var = sq * (1.0f / D_MODEL) - mu * mu;
    float rr  = rsqrtf(var + 1e-5f);
    float y   = (v - mu) * rr * gamma[c] + beta[c];
    g_h2H[(size_t)t * D_MODEL + c] = __float2half(y);
}

// ================= deform v5: quarter-warp per point, 8B loads, 4 main iterations =================
// Precompute: lane sidx (0..15) owns point sidx (corner indices pre-scaled to uint2 units
// + validity-zeroed weights); lanes 16-31 mirror. Main loop: iter it handles points
// it*4+q per quarter q; lane loads 4 corners x uint2 (4 dims). Final: reduce across
// quarters (dims are partitioned by li = lane&7, points by quarter).
__global__ void deform_kernel(const float* __restrict__ ref) {
    const int lvH[4] = {128, 64, 32, 16};
    const int lvW[4] = {128, 64, 32, 16};
    const int lvS[4] = {0, 16384, 20480, 21504};

    int g = blockIdx.x * 8 + (threadIdx.x >> 5);
    int lane = threadIdx.x & 31;
    int b  = g / (SLEN * NHEADS);
    int rm = g - b * (SLEN * NHEADS);
    int qi = rm / NHEADS;
    int h  = rm - qi * NHEADS;
    int tok = b * SLEN + qi;

    // --- scalar prefetch: 32 offsets, 8 ref floats, 16 logits ---
    float offv = g_off[(size_t)tok * 256 + h * 32 + lane];
    float refv = (lane < 8) ? ref[(size_t)tok * 8 + lane] : 0.f;
    float lg   = (lane < 16) ? g_attn[(size_t)tok * 128 + h * 16 + lane] : -1e30f;

    // softmax over 16 logits
    float mx = lg;
    #pragma unroll
    for (int o = 8; o; o >>= 1) mx = fmaxf(mx, __shfl_xor_sync(0xffffffffu, mx, o));
    float e = (lane < 16) ? __expf(lg - mx) : 0.f;
    float se = e;
    #pragma unroll
    for (int o = 8; o; o >>= 1) se += __shfl_xor_sync(0xffffffffu, se, o);
    float wnorm = e / se;

    // --- precompute: lane sidx owns point sidx; corner indices pre-scaled by 8 (uint2/row) ---
    uint32_t c00, c01, c10, c11;
    float w00, w01, w10, w11;
    {
        const int sidx = lane & 15;
        const int lvl  = sidx >> 2;
        const int Ww = lvW[lvl], Hh = lvH[lvl];
        float rx = __shfl_sync(0xffffffffu, refv, lvl * 2 + 0);
        float ry = __shfl_sync(0xffffffffu, refv, lvl * 2 + 1);
        float ox = __shfl_sync(0xffffffffu, offv, sidx * 2 + 0);
        float oy = __shfl_sync(0xffffffffu, offv, sidx * 2 + 1);
        float w  = __shfl_sync(0xffffffffu, wnorm, sidx);

        float x = fmaf(rx, (float)Ww, ox) - 0.5f;
        float y = fmaf(ry, (float)Hh, oy) - 0.5f;
        float x0f = floorf(x), y0f = floorf(y);
        int x0 = (int)x0f, y0 = (int)y0f;
        float wx = x - x0f, wy = y - y0f;
        int x1 = x0 + 1, y1 = y0 + 1;

        float vx0 = ((unsigned)x0 < (unsigned)Ww) ? 1.f : 0.f;
        float vx1 = ((unsigned)x1 < (unsigned)Ww) ? 1.f : 0.f;
        float vy0 = ((unsigned)y0 < (unsigned)Hh) ? 1.f : 0.f;
        float vy1 = ((unsigned)y1 < (unsigned)Hh) ? 1.f : 0.f;

        int x0c = min(max(x0, 0), Ww - 1), x1c = min(max(x1, 0), Ww - 1);
        int y0c = min(max(y0, 0), Hh - 1), y1c = min(max(y1, 0), Hh - 1);

        uint32_t pb = (uint32_t)h * NTOK + (uint32_t)(b * SLEN + lvS[lvl]);
        uint32_t r0 = pb + (uint32_t)(y0c * Ww), r1 = pb + (uint32_t)(y1c * Ww);
        c00 = (r0 + (uint32_t)x0c) * 8u; c01 = (r0 + (uint32_t)x1c) * 8u;
        c10 = (r1 + (uint32_t)x0c) * 8u; c11 = (r1 + (uint32_t)x1c) * 8u;

        float wx0 = 1.f - wx, wy0 = 1.f - wy;
        w00 = w * wx0 * wy0 * (vx0 * vy0);
        w01 = w * wx  * wy0 * (vx1 * vy0);
        w10 = w * wx0 * wy  * (vx0 * vy1);
        w11 = w * wx  * wy  * (vx1 * vy1);
    }

    // --- main loop: quarter q handles points {q, q+4, q+8, q+12}; lane covers dims 4*li..4*li+3 ---
    const int q = lane >> 3;
    const uint32_t li = (uint32_t)(lane & 7);
    const uint2* vbase = (const uint2*)g_valueH;
    float4 acc = make_float4(0.f, 0.f, 0.f, 0.f);
    #pragma unroll
    for (int it = 0; it < 4; it++) {
        const int sp = it * 4 + q;
        uint32_t a00 = __shfl_sync(0xffffffffu, c00, sp) + li;
        uint32_t a01 = __shfl_sync(0xffffffffu, c01, sp) + li;
        uint32_t a10 = __shfl_sync(0xffffffffu, c10, sp) + li;
        uint32_t a11 = __shfl_sync(0xffffffffu, c11, sp) + li;
        float u00 = __shfl_sync(0xffffffffu, w00, sp);
        float u01 = __shfl_sync(0xffffffffu, w01, sp);
        float u10 = __shfl_sync(0xffffffffu, w10, sp);
        float u11 = __shfl_sync(0xffffffffu, w11, sp);
        uint2 r00 = vbase[a00];
        uint2 r01 = vbase[a01];
        uint2 r10 = vbase[a10];
        uint2 r11 = vbase[a11];
        float2 f0, f1;
        f0 = __half22float2(*(const __half2*)&r00.x); f1 = __half22float2(*(const __half2*)&r00.y);
        acc.x += f0.x * u00; acc.y += f0.y * u00; acc.z += f1.x * u00; acc.w += f1.y * u00;
        f0 = __half22float2(*(const __half2*)&r01.x); f1 = __half22float2(*(const __half2*)&r01.y);
        acc.x += f0.x * u01; acc.y += f0.y * u01; acc.z += f1.x * u01; acc.w += f1.y * u01;
        f0 = __half22float2(*(const __half2*)&r10.x); f1 = __half22float2(*(const __half2*)&r10.y);
        acc.x += f0.x * u10; acc.y += f0.y * u10; acc.z += f1.x * u10; acc.w += f1.y * u10;
        f0 = __half22float2(*(const __half2*)&r11.x); f1 = __half22float2(*(const __half2*)&r11.y);
        acc.x += f0.x * u11; acc.y += f0.y * u11; acc.z += f1.x * u11; acc.w += f1.y * u11;
    }
    // reduce across the 4 quarters (same dims, different points)
    #pragma unroll
    for (int o = 8; o <= 16; o <<= 1) {
        acc.x += __shfl_xor_sync(0xffffffffu, acc.x, o);
        acc.y += __shfl_xor_sync(0xffffffffu, acc.y, o);
        acc.z += __shfl_xor_sync(0xffffffffu, acc.z, o);
        acc.w += __shfl_xor_sync(0xffffffffu, acc.w, o);
    }
    if (lane < 8) {
        uint2 outv;
        __half2 h0 = __floats2half2_rn(acc.x, acc.y);
        __half2 h1 = __floats2half2_rn(acc.z, acc.w);
        outv.x = *(const uint32_t*)&h0;
        outv.y = *(const uint32_t*)&h1;
        ((uint2*)g_sampH)[(uint32_t)tok * 64u + (uint32_t)h * 8u + li] = outv;
    }
}

// ================= launch =================
extern "C" void kernel_launch(void* const* d_in, const int* in_sizes, int n_in,
                              void* d_out, int out_size) {
    const float* src  = (const float*)d_in[0];
    const float* pos  = (const float*)d_in[1];
    const float* refp = (const float*)d_in[2];
    const float* n1g = (const float*)d_in[5];
    const float* n1b = (const float*)d_in[6];
    const float* n2g = (const float*)d_in[7];
    const float* n2b = (const float*)d_in[8];
    const float* Wv  = (const float*)d_in[9];
    const float* bv  = (const float*)d_in[10];
    const float* Wo  = (const float*)d_in[11];
    const float* bo  = (const float*)d_in[12];
    const float* Wa  = (const float*)d_in[13];
    const float* ba  = (const float*)d_in[14];
    const float* Wout= (const float*)d_in[15];
    const float* bout= (const float*)d_in[16];
    const float* Wf1 = (const float*)d_in[17];
    const float* bf1 = (const float*)d_in[18];
    const float* Wf2 = (const float*)d_in[19];
    const float* bf2 = (const float*)d_in[20];
    float* out = (float*)d_out;

    __half *srcH, *qH, *sampH, *h2H, *ffnH, *valH;
    __half *wv, *wqa, *wo, *wf1, *wf2;
    float *pOff, *pAttn, *pSrc2;
    cudaGetSymbolAddress((void**)&srcH, g_srcH);
    cudaGetSymbolAddress((void**)&qH,   g_qH);
    cudaGetSymbolAddress((void**)&sampH,g_sampH);
    cudaGetSymbolAddress((void**)&h2H,  g_h2H);
    cudaGetSymbolAddress((void**)&ffnH, g_ffnH);
    cudaGetSymbolAddress((void**)&valH, g_valueH);
    cudaGetSymbolAddress((void**)&wv,   w_v);
    cudaGetSymbolAddress((void**)&wqa,  w_qa);
    cudaGetSymbolAddress((void**)&wo,   w_o);
    cudaGetSymbolAddress((void**)&wf1,  w_f1);
    cudaGetSymbolAddress((void**)&wf2,  w_f2);
    cudaGetSymbolAddress((void**)&pOff,  g_off);
    cudaGetSymbolAddress((void**)&pAttn, g_attn);
    cudaGetSymbolAddress((void**)&pSrc2, g_src2);

    cudaFuncSetAttribute(mma_gemm<1>, cudaFuncAttributeMaxDynamicSharedMemorySize, GEMM_SMEM);
    cudaFuncSetAttribute(mma_gemm<2>, cudaFuncAttributeMaxDynamicSharedMemorySize, GEMM_SMEM);
    cudaFuncSetAttribute(mma_gemm<3>, cudaFuncAttributeMaxDynamicSharedMemorySize, GEMM_SMEM);
    cudaFuncSetAttribute(mma_gemm<4>, cudaFuncAttributeMaxDynamicSharedMemorySize, GEMM_SMEM);

    dim3 t256(256), t128(128);
    const int MB = NTOK / 128;   // 340

    pre_kernel<<<NTOK, t256>>>(src, n1g, n1b, pos,                                  // 0 (incl. wprep)
                               Wv, Wo, Wa, Wout, Wf1, Wf2);
    mma_gemm<4><<<dim3(2, MB), t128, GEMM_SMEM>>>(srcH, wv, bv, nullptr,            // 1: value (planar)
                                                  nullptr, nullptr, valH, 256, 256);
    mma_gemm<3><<<dim3(3, MB), t128, GEMM_SMEM>>>(qH, wqa, bo, ba,                  // 2: offsets+logits
                                                  pOff, pAttn, nullptr, 384, 256);
    deform_kernel<<<(NTOK * NHEADS) / 8, t256>>>(refp);                             // 3 <- profiled
    mma_gemm<2><<<dim3(2, MB), t128, GEMM_SMEM>>>(sampH, wo, bout, src,             // 4: out-proj + res
                                                  pSrc2, nullptr, nullptr, 256, 256);
    ln2_kernel<<<NTOK, t256>>>(pSrc2, n2g, n2b);                                    // 5
    mma_gemm<1><<<dim3(8, MB), t128, GEMM_SMEM>>>(h2H, wf1, bf1, nullptr,           // 6: FFN1 + gelu
                                                  nullptr, nullptr, ffnH, 1024, 256);
    mma_gemm<2><<<dim3(2, MB), t128, GEMM_SMEM>>>(ffnH, wf2, bf2, pSrc2,            // 7: FFN2 + res
                                                  out, nullptr, nullptr, 256, 1024);
}

// round 13
// speedup vs baseline: 1.6839x; 1.1650x over previous
#include <cuda_runtime.h>
#include <cuda_fp16.h>
#include <math.h>
#include <stdint.h>

#define D_MODEL 256
#define D_FFN   1024
#define NHEADS  8
#define NLEV    4
#define NPTS    4
#define HDIM    32
#define BATCH   2
#define SLEN    21760
#define NTOK    (BATCH * SLEN)   // 43520

// ================= scratch (device globals; no allocation allowed) =================
__device__ __align__(16) __half g_srcH[NTOK * D_MODEL];
__device__ __align__(16) __half g_qH[NTOK * D_MODEL];
__device__ __align__(16) __half g_sampH[NTOK * D_MODEL];
__device__ __align__(16) __half g_h2H[NTOK * D_MODEL];
__device__ __align__(16) __half g_ffnH[NTOK * D_FFN];
__device__ __align__(16) __half g_valueH[NTOK * D_MODEL];     // planar: [h][tok][dim]

__device__ float g_off[NTOK * D_MODEL];
__device__ float g_attn[NTOK * NHEADS * 16];                  // raw logits
__device__ float g_src2[NTOK * D_MODEL];

// weights transposed [N][K], fp16
__device__ __align__(16) __half w_v[256 * 256];
__device__ __align__(16) __half w_qa[384 * 256];              // 0-255: W_off, 256-383: W_attn
__device__ __align__(16) __half w_o[256 * 256];
__device__ __align__(16) __half w_f1[1024 * 256];
__device__ __align__(16) __half w_f2[256 * 1024];

// ================= helpers =================
__device__ __forceinline__ uint32_t smem_u32(const void* p) {
    uint32_t a;
    asm("{ .reg .u64 t; cvta.to.shared.u64 t, %1; cvt.u32.u64 %0, t; }" : "=r"(a) : "l"(p));
    return a;
}
__device__ __forceinline__ void ldm_x4(uint32_t* r, uint32_t addr) {
    asm volatile("ldmatrix.sync.aligned.m8n8.x4.shared.b16 {%0,%1,%2,%3}, [%4];"
                 : "=r"(r[0]), "=r"(r[1]), "=r"(r[2]), "=r"(r[3]) : "r"(addr));
}
__device__ __forceinline__ void mma16816(float* d, const uint32_t* a, const uint32_t* b) {
    asm volatile("mma.sync.aligned.m16n8k16.row.col.f32.f16.f16.f32 "
                 "{%0,%1,%2,%3}, {%4,%5,%6,%7}, {%8,%9}, {%0,%1,%2,%3};"
                 : "+f"(d[0]), "+f"(d[1]), "+f"(d[2]), "+f"(d[3])
                 : "r"(a[0]), "r"(a[1]), "r"(a[2]), "r"(a[3]), "r"(b[0]), "r"(b[1]));
}
__device__ __forceinline__ void cpa16(uint32_t dst, const void* src) {
    asm volatile("cp.async.cg.shared.global [%0], [%1], 16;" :: "r"(dst), "l"(src));
}

// ================= fp16 HMMA GEMM (R6 config): CTA 128x128, 4 warps of 64x64 =================
// 128 threads, BK=64, 3-stage cp.async ring, 2 CTAs/SM.
// EPI: 1 = gelu(x+bias) -> fp16; 2 = x+bias+aux(residual) -> fp32;
//      3 = dual (N=384): col<256 -> C(bias), col>=256 -> Cb(aux bias);
//      4 = fp16 planar value: Ch[((col>>5)*NTOK+row)*32 + (col&31)]
static const int LDSB = 144;                  // 64 fp16 (128 B) + 16 B pad
static const int BUFB = 128 * LDSB;           // 18432 B
static const int GEMM_SMEM = 6 * BUFB;        // 110592 B

template <int EPI>
__global__ void __launch_bounds__(128, 2) mma_gemm(
    const __half* __restrict__ A, const __half* __restrict__ B,
    const float* __restrict__ bias, const float* __restrict__ aux,
    float* __restrict__ C, float* __restrict__ Cb, __half* __restrict__ Ch,
    int N, int K)
{
    extern __shared__ __align__(16) char sm[];
    const uint32_t smb = smem_u32(sm);
    const int tid = threadIdx.x;
    const int wid = tid >> 5, lane = tid & 31;
    const int wm = wid >> 1, wn = wid & 1;                // 2x2 warps of 64x64
    const int m0 = blockIdx.y * 128, n0 = blockIdx.x * 128;
    const int S = K >> 6;

    float acc[4][8][4];
    #pragma unroll
    for (int i = 0; i < 4; i++)
        #pragma unroll
        for (int j = 0; j < 8; j++)
            #pragma unroll
            for (int r = 0; r < 4; r++) acc[i][j][r] = 0.f;

    auto prefetch = [&](int s) {
        int k0 = s << 6;
        const uint32_t ab = smb + (uint32_t)(s % 3) * (2u * BUFB);
        const uint32_t bb = ab + BUFB;
        #pragma unroll
        for (int i = 0; i < 16; i++) {
            int c = tid + (i << 7);                       // 0..2047
            int cc = c & 1023;
            int row = cc >> 3;
            int kc  = (cc & 7) << 3;
            uint32_t dst; const __half* src;
            if (c < 1024) {
                dst = ab + (uint32_t)(row * LDSB + kc * 2);
                src = A + (size_t)(m0 + row) * K + k0 + kc;
            } else {
                dst = bb + (uint32_t)(row * LDSB + kc * 2);
                src = B + (size_t)(n0 + row) * K + k0 + kc;
            }
            cpa16(dst, src);
        }
        asm volatile("cp.async.commit_group;");
    };

    prefetch(0);
    if (S > 1) prefetch(1);

    for (int s = 0; s < S; s++) {
        if (s + 1 < S) asm volatile("cp.async.wait_group 1;");
        else           asm volatile("cp.async.wait_group 0;");
        __syncthreads();
        if (s + 2 < S) prefetch(s + 2);

        const uint32_t ab = smb + (uint32_t)(s % 3) * (2u * BUFB);
        const uint32_t bb = ab + BUFB;
        const uint32_t aoff = ab + (uint32_t)(((lane & 15) + wm * 64) * LDSB + ((lane >> 4) << 4));
        const uint32_t boff = bb + (uint32_t)((((lane & 7) + ((lane >> 4) << 3)) + wn * 64) * LDSB
                                              + (((lane >> 3) & 1) << 4));
        #pragma unroll
        for (int ks = 0; ks < 4; ks++) {
            const uint32_t kb = (uint32_t)(ks << 5);
            uint32_t afr[4][4], bfr[8][2];
            #pragma unroll
            for (int mi = 0; mi < 4; mi++)
                ldm_x4(afr[mi], aoff + (uint32_t)(mi * 16 * LDSB) + kb);
            #pragma unroll
            for (int nj = 0; nj < 4; nj++) {
                uint32_t r[4];
                ldm_x4(r, boff + (uint32_t)(nj * 16 * LDSB) + kb);
                bfr[nj * 2][0] = r[0]; bfr[nj * 2][1] = r[1];
                bfr[nj * 2 + 1][0] = r[2]; bfr[nj * 2 + 1][1] = r[3];
            }
            #pragma unroll
            for (int mi = 0; mi < 4; mi++)
                #pragma unroll
                for (int ni = 0; ni < 8; ni++)
                    mma16816(acc[mi][ni], afr[mi], bfr[ni]);
        }
    }
    __syncthreads();

    // ---- epilogue: stage 64x64 per warp in smem (stride 68 floats), store coalesced ----
    float* ws = (float*)sm + wid * (64 * 68);
    const int er = lane >> 2, ec = (lane & 3) * 2;
    #pragma unroll
    for (int mi = 0; mi < 4; mi++)
        #pragma unroll
        for (int ni = 0; ni < 8; ni++) {
            *(float2*)&ws[(mi * 16 + er) * 68 + ni * 8 + ec]     = make_float2(acc[mi][ni][0], acc[mi][ni][1]);
            *(float2*)&ws[(mi * 16 + er + 8) * 68 + ni * 8 + ec] = make_float2(acc[mi][ni][2], acc[mi][ni][3]);
        }
    __syncwarp();

    const int gc0 = n0 + wn * 64 + lane;
    const int gc1 = gc0 + 32;
    float b0, b1;
    if (EPI == 3) {
        b0 = (gc0 < 256) ? bias[gc0] : aux[gc0 - 256];
        b1 = (gc1 < 256) ? bias[gc1] : aux[gc1 - 256];
    } else { b0 = bias[gc0]; b1 = bias[gc1]; }

    for (int r = 0; r < 64; r++) {
        const int gr = m0 + wm * 64 + r;
        float v0 = ws[r * 68 + lane] + b0;
        float v1 = ws[r * 68 + 32 + lane] + b1;
        if (EPI == 1) {
            v0 = 0.5f * v0 * (1.0f + erff(v0 * 0.70710678118654752f));
            v1 = 0.5f * v1 * (1.0f + erff(v1 * 0.70710678118654752f));
            Ch[(size_t)gr * N + gc0] = __float2half(v0);
            Ch[(size_t)gr * N + gc1] = __float2half(v1);
        } else if (EPI == 2) {
            C[(size_t)gr * N + gc0] = v0 + aux[(size_t)gr * N + gc0];
            C[(size_t)gr * N + gc1] = v1 + aux[(size_t)gr * N + gc1];
        } else if (EPI == 3) {
            if (gc0 < 256) C[(size_t)gr * 256 + gc0] = v0;
            else           Cb[(size_t)gr * 128 + (gc0 - 256)] = v0;
            if (gc1 < 256) C[(size_t)gr * 256 + gc1] = v1;
            else           Cb[(size_t)gr * 128 + (gc1 - 256)] = v1;
        } else {  // EPI == 4: planar value
            Ch[((size_t)(gc0 >> 5) * NTOK + gr) * 32 + (gc0 & 31)] = __float2half(v0);
            Ch[((size_t)(gc1 >> 5) * NTOK + gr) * 32 + (gc1 & 31)] = __float2half(v1);
        }
    }
}

// ================= pre v2: warp-per-token (no smem/barrier) + weight prep slice =================
// grid = NTOK/8, block 256 (8 warps). Warp w handles token blockIdx.x*8+w.
__global__ void pre_kernel(const float* __restrict__ x,
                           const float* __restrict__ gamma,
                           const float* __restrict__ beta,
                           const float* __restrict__ pos,
                           const float* __restrict__ Wv, const float* __restrict__ Wo,
                           const float* __restrict__ Wa, const float* __restrict__ Wout,
                           const float* __restrict__ Wf1, const float* __restrict__ Wf2) {
    const int wid = threadIdx.x >> 5, lane = threadIdx.x & 31;
    const int t = blockIdx.x * 8 + wid;

    // ---- weight prep slice (753664 = weights total; grid*256 = 1.39M threads) ----
    int gid = blockIdx.x * 256 + threadIdx.x;
    if (gid < 753664) {
        int i = gid;
        const float* W; __half* B; int K, N, rowOff, i2;
        if (i < 65536)        { W = Wv;  B = w_v;  K = 256;  N = 256;  rowOff = 0;   i2 = i; }
        else if (i < 131072)  { W = Wo;  B = w_qa; K = 256;  N = 256;  rowOff = 0;   i2 = i - 65536; }
        else if (i < 163840)  { W = Wa;  B = w_qa; K = 256;  N = 128;  rowOff = 256; i2 = i - 131072; }
        else if (i < 229376)  { W = Wout;B = w_o;  K = 256;  N = 256;  rowOff = 0;   i2 = i - 163840; }
        else if (i < 491520)  { W = Wf1; B = w_f1; K = 256;  N = 1024; rowOff = 0;   i2 = i - 229376; }
        else                  { W = Wf2; B = w_f2; K = 1024; N = 256;  rowOff = 0;   i2 = i - 491520; }
        int k = i2 / N, n = i2 - k * N;
        B[(size_t)(n + rowOff) * K + k] = __float2half(W[i2]);
    }

    // ---- per-token LN1 + pos, warp-wide ----
    const float4* rowX = (const float4*)(x + (size_t)t * 256);
    float4 va = rowX[lane], vb = rowX[lane + 32];

    // src -> fp16
    {
        uint2 o0, o1;
        __half2 p0 = __floats2half2_rn(va.x, va.y), p1 = __floats2half2_rn(va.z, va.w);
        __half2 p2 = __floats2half2_rn(vb.x, vb.y), p3 = __floats2half2_rn(vb.z, vb.w);
        o0.x = *(uint32_t*)&p0; o0.y = *(uint32_t*)&p1;
        o1.x = *(uint32_t*)&p2; o1.y = *(uint32_t*)&p3;
        ((uint2*)g_srcH)[(size_t)t * 64 + lane] = o0;
        ((uint2*)g_srcH)[(size_t)t * 64 + 32 + lane] = o1;
    }

    float s  = va.x + va.y + va.z + va.w + vb.x + vb.y + vb.z + vb.w;
    float s2 = va.x*va.x + va.y*va.y + va.z*va.z + va.w*va.w
             + vb.x*vb.x + vb.y*vb.y + vb.z*vb.z + vb.w*vb.w;
    #pragma unroll
    for (int o = 16; o; o >>= 1) {
        s  += __shfl_xor_sync(0xffffffffu, s,  o);
        s2 += __shfl_xor_sync(0xffffffffu, s2, o);
    }
    float mu  = s * (1.0f / D_MODEL);
    float var = s2 * (1.0f / D_MODEL) - mu * mu;
    float rr  = rsqrtf(var + 1e-5f);

    const float4* rowP = (const float4*)(pos + (size_t)t * 256);
    const float4* gmA = (const float4*)gamma;
    const float4* btA = (const float4*)beta;
    #pragma unroll
    for (int hfl = 0; hfl < 2; hfl++) {
        int idx = lane + hfl * 32;
        float4 v = hfl ? vb : va;
        float4 p = rowP[idx];
        float4 gm = gmA[idx], bt = btA[idx];
        float y0 = (v.x - mu) * rr * gm.x + bt.x + p.x;
        float y1 = (v.y - mu) * rr * gm.y + bt.y + p.y;
        float y2 = (v.z - mu) * rr * gm.z + bt.z + p.z;
        float y3 = (v.w - mu) * rr * gm.w + bt.w + p.w;
        uint2 o;
        __half2 q0 = __floats2half2_rn(y0, y1), q1 = __floats2half2_rn(y2, y3);
        o.x = *(uint32_t*)&q0; o.y = *(uint32_t*)&q1;
        ((uint2*)g_qH)[(size_t)t * 64 + idx] = o;
    }
}

// ================= ln2 v2: warp-per-token =================
__global__ void ln2_kernel(const float* __restrict__ x,
                           const float* __restrict__ gamma,
                           const float* __restrict__ beta) {
    const int wid = threadIdx.x >> 5, lane = threadIdx.x & 31;
    const int t = blockIdx.x * 8 + wid;

    const float4* rowX = (const float4*)(x + (size_t)t * 256);
    float4 va = rowX[lane], vb = rowX[lane + 32];

    float s  = va.x + va.y + va.z + va.w + vb.x + vb.y + vb.z + vb.w;
    float s2 = va.x*va.x + va.y*va.y + va.z*va.z + va.w*va.w
             + vb.x*vb.x + vb.y*vb.y + vb.z*vb.z + vb.w*vb.w;
    #pragma unroll
    for (int o = 16; o; o >>= 1) {
        s  += __shfl_xor_sync(0xffffffffu, s,  o);
        s2 += __shfl_xor_sync(0xffffffffu, s2, o);
    }
    float mu  = s * (1.0f / D_MODEL);
    float var = s2 * (1.0f / D_MODEL) - mu * mu;
    float rr  = rsqrtf(var + 1e-5f);

    const float4* gmA = (const float4*)gamma;
    const float4* btA = (const float4*)beta;
    #pragma unroll
    for (int hfl = 0; hfl < 2; hfl++) {
        int idx = lane + hfl * 32;
        float4 v = hfl ? vb : va;
        float4 gm = gmA[idx], bt = btA[idx];
        float y0 = (v.x - mu) * rr * gm.x + bt.x;
        float y1 = (v.y - mu) * rr * gm.y + bt.y;
        float y2 = (v.z - mu) * rr * gm.z + bt.z;
        float y3 = (v.w - mu) * rr * gm.w + bt.w;
        uint2 o;
        __half2 q0 = __floats2half2_rn(y0, y1), q1 = __floats2half2_rn(y2, y3);
        o.x = *(uint32_t*)&q0; o.y = *(uint32_t*)&q1;
        ((uint2*)g_h2H)[(size_t)t * 64 + idx] = o;
    }
}

// ================= deform v6: fp16 bilinear blend (HFMA2), fp32 point accumulation =================
// Precompute: lane sidx (0..15) owns point sidx: corner indices (uint2 units) +
// half2-broadcast bilinear weights (validity-zeroed) + fp32 attention weight.
// Main loop: quarter-warp per point, 4 iterations, 4x LDG.64 per lane per iter.
__global__ void deform_kernel(const float* __restrict__ ref) {
    const int lvH[4] = {128, 64, 32, 16};
    const int lvW[4] = {128, 64, 32, 16};
    const int lvS[4] = {0, 16384, 20480, 21504};

    int g = blockIdx.x * 8 + (threadIdx.x >> 5);
    int lane = threadIdx.x & 31;
    int b  = g / (SLEN * NHEADS);
    int rm = g - b * (SLEN * NHEADS);
    int qi = rm / NHEADS;
    int h  = rm - qi * NHEADS;
    int tok = b * SLEN + qi;

    // --- scalar prefetch: 32 offsets, 8 ref floats, 16 logits ---
    float offv = g_off[(size_t)tok * 256 + h * 32 + lane];
    float refv = (lane < 8) ? ref[(size_t)tok * 8 + lane] : 0.f;
    float lg   = (lane < 16) ? g_attn[(size_t)tok * 128 + h * 16 + lane] : -1e30f;

    // softmax over 16 logits
    float mx = lg;
    #pragma unroll
    for (int o = 8; o; o >>= 1) mx = fmaxf(mx, __shfl_xor_sync(0xffffffffu, mx, o));
    float e = (lane < 16) ? __expf(lg - mx) : 0.f;
    float se = e;
    #pragma unroll
    for (int o = 8; o; o >>= 1) se += __shfl_xor_sync(0xffffffffu, se, o);
    float wnorm = e / se;

    // --- precompute: lane sidx owns point sidx; half2-packed bilinear weights ---
    uint32_t c00, c01, c10, c11;
    uint32_t uh00, uh01, uh10, uh11;
    float wat;
    {
        const int sidx = lane & 15;
        const int lvl  = sidx >> 2;
        const int Ww = lvW[lvl], Hh = lvH[lvl];
        float rx = __shfl_sync(0xffffffffu, refv, lvl * 2 + 0);
        float ry = __shfl_sync(0xffffffffu, refv, lvl * 2 + 1);
        float ox = __shfl_sync(0xffffffffu, offv, sidx * 2 + 0);
        float oy = __shfl_sync(0xffffffffu, offv, sidx * 2 + 1);
        wat = __shfl_sync(0xffffffffu, wnorm, sidx);

        float x = fmaf(rx, (float)Ww, ox) - 0.5f;
        float y = fmaf(ry, (float)Hh, oy) - 0.5f;
        float x0f = floorf(x), y0f = floorf(y);
        int x0 = (int)x0f, y0 = (int)y0f;
        float wx = x - x0f, wy = y - y0f;
        int x1 = x0 + 1, y1 = y0 + 1;

        float vx0 = ((unsigned)x0 < (unsigned)Ww) ? 1.f : 0.f;
        float vx1 = ((unsigned)x1 < (unsigned)Ww) ? 1.f : 0.f;
        float vy0 = ((unsigned)y0 < (unsigned)Hh) ? 1.f : 0.f;
        float vy1 = ((unsigned)y1 < (unsigned)Hh) ? 1.f : 0.f;

        int x0c = min(max(x0, 0), Ww - 1), x1c = min(max(x1, 0), Ww - 1);
        int y0c = min(max(y0, 0), Hh - 1), y1c = min(max(y1, 0), Hh - 1);

        uint32_t pb = (uint32_t)h * NTOK + (uint32_t)(b * SLEN + lvS[lvl]);
        uint32_t r0 = pb + (uint32_t)(y0c * Ww), r1 = pb + (uint32_t)(y1c * Ww);
        c00 = (r0 + (uint32_t)x0c) * 8u; c01 = (r0 + (uint32_t)x1c) * 8u;
        c10 = (r1 + (uint32_t)x0c) * 8u; c11 = (r1 + (uint32_t)x1c) * 8u;

        float wx0 = 1.f - wx, wy0 = 1.f - wy;
        __half2 t0 = __float2half2_rn(wx0 * wy0 * (vx0 * vy0));
        __half2 t1 = __float2half2_rn(wx  * wy0 * (vx1 * vy0));
        __half2 t2 = __float2half2_rn(wx0 * wy  * (vx0 * vy1));
        __half2 t3 = __float2half2_rn(wx  * wy  * (vx1 * vy1));
        uh00 = *(uint32_t*)&t0; uh01 = *(uint32_t*)&t1;
        uh10 = *(uint32_t*)&t2; uh11 = *(uint32_t*)&t3;
    }

    // --- main loop: quarter q handles points {q, q+4, q+8, q+12}; lane covers dims 4*li..4*li+3 ---
    const int q = lane >> 3;
    const uint32_t li = (uint32_t)(lane & 7);
    const uint2* vbase = (const uint2*)g_valueH;
    float4 acc = make_float4(0.f, 0.f, 0.f, 0.f);
    #pragma unroll
    for (int it = 0; it < 4; it++) {
        const int sp = it * 4 + q;
        uint32_t a00 = __shfl_sync(0xffffffffu, c00, sp) + li;
        uint32_t a01 = __shfl_sync(0xffffffffu, c01, sp) + li;
        uint32_t a10 = __shfl_sync(0xffffffffu, c10, sp) + li;
        uint32_t a11 = __shfl_sync(0xffffffffu, c11, sp) + li;
        uint32_t b00 = __shfl_sync(0xffffffffu, uh00, sp);
        uint32_t b01 = __shfl_sync(0xffffffffu, uh01, sp);
        uint32_t b10 = __shfl_sync(0xffffffffu, uh10, sp);
        uint32_t b11 = __shfl_sync(0xffffffffu, uh11, sp);
        float w = __shfl_sync(0xffffffffu, wat, sp);
        uint2 r00 = vbase[a00];
        uint2 r01 = vbase[a01];
        uint2 r10 = vbase[a10];
        uint2 r11 = vbase[a11];
        // fp16 bilinear blend (weights sum to <=1; values fp16 already)
        __half2 blo = __hmul2(*(__half2*)&b00, *(__half2*)&r00.x);
        blo = __hfma2(*(__half2*)&b01, *(__half2*)&r01.x, blo);
        blo = __hfma2(*(__half2*)&b10, *(__half2*)&r10.x, blo);
        blo = __hfma2(*(__half2*)&b11, *(__half2*)&r11.x, blo);
        __half2 bhi = __hmul2(*(__half2*)&b00, *(__half2*)&r00.y);
        bhi = __hfma2(*(__half2*)&b01, *(__half2*)&r01.y, bhi);
        bhi = __hfma2(*(__half2*)&b10, *(__half2*)&r10.y, bhi);
        bhi = __hfma2(*(__half2*)&b11, *(__half2*)&r11.y, bhi);
        float2 f0 = __half22float2(blo);
        float2 f1 = __half22float2(bhi);
        acc.x = fmaf(f0.x, w, acc.x);
        acc.y = fmaf(f0.y, w, acc.y);
        acc.z = fmaf(f1.x, w, acc.z);
        acc.w = fmaf(f1.y, w, acc.w);
    }
    // reduce across the 4 quarters (same dims, different points)
    #pragma unroll
    for (int o = 8; o <= 16; o <<= 1) {
        acc.x += __shfl_xor_sync(0xffffffffu, acc.x, o);
        acc.y += __shfl_xor_sync(0xffffffffu, acc.y, o);
        acc.z += __shfl_xor_sync(0xffffffffu, acc.z, o);
        acc.w += __shfl_xor_sync(0xffffffffu, acc.w, o);
    }
    if (lane < 8) {
        uint2 outv;
        __half2 h0 = __floats2half2_rn(acc.x, acc.y);
        __half2 h1 = __floats2half2_rn(acc.z, acc.w);
        outv.x = *(const uint32_t*)&h0;
        outv.y = *(const uint32_t*)&h1;
        ((uint2*)g_sampH)[(uint32_t)tok * 64u + (uint32_t)h * 8u + li] = outv;
    }
}

// ================= launch =================
extern "C" void kernel_launch(void* const* d_in, const int* in_sizes, int n_in,
                              void* d_out, int out_size) {
    const float* src  = (const float*)d_in[0];
    const float* pos  = (const float*)d_in[1];
    const float* refp = (const float*)d_in[2];
    const float* n1g = (const float*)d_in[5];
    const float* n1b = (const float*)d_in[6];
    const float* n2g = (const float*)d_in[7];
    const float* n2b = (const float*)d_in[8];
    const float* Wv  = (const float*)d_in[9];
    const float* bv  = (const float*)d_in[10];
    const float* Wo  = (const float*)d_in[11];
    const float* bo  = (const float*)d_in[12];
    const float* Wa  = (const float*)d_in[13];
    const float* ba  = (const float*)d_in[14];
    const float* Wout= (const float*)d_in[15];
    const float* bout= (const float*)d_in[16];
    const float* Wf1 = (const float*)d_in[17];
    const float* bf1 = (const float*)d_in[18];
    const float* Wf2 = (const float*)d_in[19];
    const float* bf2 = (const float*)d_in[20];
    float* out = (float*)d_out;

    __half *srcH, *qH, *sampH, *h2H, *ffnH, *valH;
    __half *wv, *wqa, *wo, *wf1, *wf2;
    float *pOff, *pAttn, *pSrc2;
    cudaGetSymbolAddress((void**)&srcH, g_srcH);
    cudaGetSymbolAddress((void**)&qH,   g_qH);
    cudaGetSymbolAddress((void**)&sampH,g_sampH);
    cudaGetSymbolAddress((void**)&h2H,  g_h2H);
    cudaGetSymbolAddress((void**)&ffnH, g_ffnH);
    cudaGetSymbolAddress((void**)&valH, g_valueH);
    cudaGetSymbolAddress((void**)&wv,   w_v);
    cudaGetSymbolAddress((void**)&wqa,  w_qa);
    cudaGetSymbolAddress((void**)&wo,   w_o);
    cudaGetSymbolAddress((void**)&wf1,  w_f1);
    cudaGetSymbolAddress((void**)&wf2,  w_f2);
    cudaGetSymbolAddress((void**)&pOff,  g_off);
    cudaGetSymbolAddress((void**)&pAttn, g_attn);
    cudaGetSymbolAddress((void**)&pSrc2, g_src2);

    cudaFuncSetAttribute(mma_gemm<1>, cudaFuncAttributeMaxDynamicSharedMemorySize, GEMM_SMEM);
    cudaFuncSetAttribute(mma_gemm<2>, cudaFuncAttributeMaxDynamicSharedMemorySize, GEMM_SMEM);
    cudaFuncSetAttribute(mma_gemm<3>, cudaFuncAttributeMaxDynamicSharedMemorySize, GEMM_SMEM);
    cudaFuncSetAttribute(mma_gemm<4>, cudaFuncAttributeMaxDynamicSharedMemorySize, GEMM_SMEM);

    dim3 t256(256), t128(128);
    const int MB = NTOK / 128;   // 340

    pre_kernel<<<NTOK / 8, t256>>>(src, n1g, n1b, pos,                              // 0 (incl. wprep)
                                   Wv, Wo, Wa, Wout, Wf1, Wf2);
    mma_gemm<4><<<dim3(2, MB), t128, GEMM_SMEM>>>(srcH, wv, bv, nullptr,            // 1: value (planar)
                                                  nullptr, nullptr, valH, 256, 256);
    mma_gemm<3><<<dim3(3, MB), t128, GEMM_SMEM>>>(qH, wqa, bo, ba,                  // 2: offsets+logits
                                                  pOff, pAttn, nullptr, 384, 256);
    deform_kernel<<<(NTOK * NHEADS) / 8, t256>>>(refp);                             // 3 <- profiled
    mma_gemm<2><<<dim3(2, MB), t128, GEMM_SMEM>>>(sampH, wo, bout, src,             // 4: out-proj + res
                                                  pSrc2, nullptr, nullptr, 256, 256);
    ln2_kernel<<<NTOK / 8, t256>>>(pSrc2, n2g, n2b);                                // 5
    mma_gemm<1><<<dim3(8, MB), t128, GEMM_SMEM>>>(h2H, wf1, bf1, nullptr,           // 6: FFN1 + gelu
                                                  nullptr, nullptr, ffnH, 1024, 256);
    mma_gemm<2><<<dim3(2, MB), t128, GEMM_SMEM>>>(ffnH, wf2, bf2, pSrc2,            // 7: FFN2 + res
                                                  out, nullptr, nullptr, 256, 1024);
}

// round 14
// speedup vs baseline: 1.7314x; 1.0282x over previous
#include <cuda_runtime.h>
#include <cuda_fp16.h>
#include <math.h>
#include <stdint.h>

#define D_MODEL 256
#define D_FFN   1024
#define NHEADS  8
#define NLEV    4
#define NPTS    4
#define HDIM    32
#define BATCH   2
#define SLEN    21760
#define NTOK    (BATCH * SLEN)   // 43520

// ================= scratch (device globals; no allocation allowed) =================
__device__ __align__(16) __half g_srcH[NTOK * D_MODEL];
__device__ __align__(16) __half g_qH[NTOK * D_MODEL];
__device__ __align__(16) __half g_sampH[NTOK * D_MODEL];
__device__ __align__(16) __half g_h2H[NTOK * D_MODEL];
__device__ __align__(16) __half g_ffnH[NTOK * D_FFN];
__device__ __align__(16) __half g_valueH[NTOK * D_MODEL];     // planar: [h][tok][dim]

__device__ float g_off[NTOK * D_MODEL];
__device__ float g_attn[NTOK * NHEADS * 16];                  // raw logits
__device__ float g_src2[NTOK * D_MODEL];

// weights transposed [N][K], fp16
__device__ __align__(16) __half w_v[256 * 256];
__device__ __align__(16) __half w_qa[384 * 256];              // 0-255: W_off, 256-383: W_attn
__device__ __align__(16) __half w_o[256 * 256];
__device__ __align__(16) __half w_f1[1024 * 256];
__device__ __align__(16) __half w_f2[256 * 1024];

// ================= helpers =================
__device__ __forceinline__ uint32_t smem_u32(const void* p) {
    uint32_t a;
    asm("{ .reg .u64 t; cvta.to.shared.u64 t, %1; cvt.u32.u64 %0, t; }" : "=r"(a) : "l"(p));
    return a;
}
__device__ __forceinline__ void ldm_x4(uint32_t* r, uint32_t addr) {
    asm volatile("ldmatrix.sync.aligned.m8n8.x4.shared.b16 {%0,%1,%2,%3}, [%4];"
                 : "=r"(r[0]), "=r"(r[1]), "=r"(r[2]), "=r"(r[3]) : "r"(addr));
}
__device__ __forceinline__ void mma16816(float* d, const uint32_t* a, const uint32_t* b) {
    asm volatile("mma.sync.aligned.m16n8k16.row.col.f32.f16.f16.f32 "
                 "{%0,%1,%2,%3}, {%4,%5,%6,%7}, {%8,%9}, {%0,%1,%2,%3};"
                 : "+f"(d[0]), "+f"(d[1]), "+f"(d[2]), "+f"(d[3])
                 : "r"(a[0]), "r"(a[1]), "r"(a[2]), "r"(a[3]), "r"(b[0]), "r"(b[1]));
}
__device__ __forceinline__ void cpa16(uint32_t dst, const void* src) {
    asm volatile("cp.async.cg.shared.global [%0], [%1], 16;" :: "r"(dst), "l"(src));
}

// ================= fp16 HMMA GEMM (R6 config): CTA 128x128, 4 warps of 64x64 =================
// 128 threads, BK=64, 3-stage cp.async ring, 2 CTAs/SM.
// EPI: 1 = gelu(x+bias) -> fp16; 2 = x+bias+aux(residual) -> fp32;
//      3 = dual (N=384): col<256 -> C(bias), col>=256 -> Cb(aux bias);
//      4 = fp16 planar value: Ch[((col>>5)*NTOK+row)*32 + (col&31)]  (Ch pre-offset for batch)
static const int LDSB = 144;                  // 64 fp16 (128 B) + 16 B pad
static const int BUFB = 128 * LDSB;           // 18432 B
static const int GEMM_SMEM = 6 * BUFB;        // 110592 B

template <int EPI>
__global__ void __launch_bounds__(128, 2) mma_gemm(
    const __half* __restrict__ A, const __half* __restrict__ B,
    const float* __restrict__ bias, const float* __restrict__ aux,
    float* __restrict__ C, float* __restrict__ Cb, __half* __restrict__ Ch,
    int N, int K)
{
    extern __shared__ __align__(16) char sm[];
    const uint32_t smb = smem_u32(sm);
    const int tid = threadIdx.x;
    const int wid = tid >> 5, lane = tid & 31;
    const int wm = wid >> 1, wn = wid & 1;                // 2x2 warps of 64x64
    const int m0 = blockIdx.y * 128, n0 = blockIdx.x * 128;
    const int S = K >> 6;

    float acc[4][8][4];
    #pragma unroll
    for (int i = 0; i < 4; i++)
        #pragma unroll
        for (int j = 0; j < 8; j++)
            #pragma unroll
            for (int r = 0; r < 4; r++) acc[i][j][r] = 0.f;

    auto prefetch = [&](int s) {
        int k0 = s << 6;
        const uint32_t ab = smb + (uint32_t)(s % 3) * (2u * BUFB);
        const uint32_t bb = ab + BUFB;
        #pragma unroll
        for (int i = 0; i < 16; i++) {
            int c = tid + (i << 7);                       // 0..2047
            int cc = c & 1023;
            int row = cc >> 3;
            int kc  = (cc & 7) << 3;
            uint32_t dst; const __half* src;
            if (c < 1024) {
                dst = ab + (uint32_t)(row * LDSB + kc * 2);
                src = A + (size_t)(m0 + row) * K + k0 + kc;
            } else {
                dst = bb + (uint32_t)(row * LDSB + kc * 2);
                src = B + (size_t)(n0 + row) * K + k0 + kc;
            }
            cpa16(dst, src);
        }
        asm volatile("cp.async.commit_group;");
    };

    prefetch(0);
    if (S > 1) prefetch(1);

    for (int s = 0; s < S; s++) {
        if (s + 1 < S) asm volatile("cp.async.wait_group 1;");
        else           asm volatile("cp.async.wait_group 0;");
        __syncthreads();
        if (s + 2 < S) prefetch(s + 2);

        const uint32_t ab = smb + (uint32_t)(s % 3) * (2u * BUFB);
        const uint32_t bb = ab + BUFB;
        const uint32_t aoff = ab + (uint32_t)(((lane & 15) + wm * 64) * LDSB + ((lane >> 4) << 4));
        const uint32_t boff = bb + (uint32_t)((((lane & 7) + ((lane >> 4) << 3)) + wn * 64) * LDSB
                                              + (((lane >> 3) & 1) << 4));
        #pragma unroll
        for (int ks = 0; ks < 4; ks++) {
            const uint32_t kb = (uint32_t)(ks << 5);
            uint32_t afr[4][4], bfr[8][2];
            #pragma unroll
            for (int mi = 0; mi < 4; mi++)
                ldm_x4(afr[mi], aoff + (uint32_t)(mi * 16 * LDSB) + kb);
            #pragma unroll
            for (int nj = 0; nj < 4; nj++) {
                uint32_t r[4];
                ldm_x4(r, boff + (uint32_t)(nj * 16 * LDSB) + kb);
                bfr[nj * 2][0] = r[0]; bfr[nj * 2][1] = r[1];
                bfr[nj * 2 + 1][0] = r[2]; bfr[nj * 2 + 1][1] = r[3];
            }
            #pragma unroll
            for (int mi = 0; mi < 4; mi++)
                #pragma unroll
                for (int ni = 0; ni < 8; ni++)
                    mma16816(acc[mi][ni], afr[mi], bfr[ni]);
        }
    }
    __syncthreads();

    // ---- epilogue: stage 64x64 per warp in smem (stride 68 floats), store coalesced ----
    float* ws = (float*)sm + wid * (64 * 68);
    const int er = lane >> 2, ec = (lane & 3) * 2;
    #pragma unroll
    for (int mi = 0; mi < 4; mi++)
        #pragma unroll
        for (int ni = 0; ni < 8; ni++) {
            *(float2*)&ws[(mi * 16 + er) * 68 + ni * 8 + ec]     = make_float2(acc[mi][ni][0], acc[mi][ni][1]);
            *(float2*)&ws[(mi * 16 + er + 8) * 68 + ni * 8 + ec] = make_float2(acc[mi][ni][2], acc[mi][ni][3]);
        }
    __syncwarp();

    const int gc0 = n0 + wn * 64 + lane;
    const int gc1 = gc0 + 32;
    float b0, b1;
    if (EPI == 3) {
        b0 = (gc0 < 256) ? bias[gc0] : aux[gc0 - 256];
        b1 = (gc1 < 256) ? bias[gc1] : aux[gc1 - 256];
    } else { b0 = bias[gc0]; b1 = bias[gc1]; }

    for (int r = 0; r < 64; r++) {
        const int gr = m0 + wm * 64 + r;
        float v0 = ws[r * 68 + lane] + b0;
        float v1 = ws[r * 68 + 32 + lane] + b1;
        if (EPI == 1) {
            v0 = 0.5f * v0 * (1.0f + erff(v0 * 0.70710678118654752f));
            v1 = 0.5f * v1 * (1.0f + erff(v1 * 0.70710678118654752f));
            Ch[(size_t)gr * N + gc0] = __float2half(v0);
            Ch[(size_t)gr * N + gc1] = __float2half(v1);
        } else if (EPI == 2) {
            C[(size_t)gr * N + gc0] = v0 + aux[(size_t)gr * N + gc0];
            C[(size_t)gr * N + gc1] = v1 + aux[(size_t)gr * N + gc1];
        } else if (EPI == 3) {
            if (gc0 < 256) C[(size_t)gr * 256 + gc0] = v0;
            else           Cb[(size_t)gr * 128 + (gc0 - 256)] = v0;
            if (gc1 < 256) C[(size_t)gr * 256 + gc1] = v1;
            else           Cb[(size_t)gr * 128 + (gc1 - 256)] = v1;
        } else {  // EPI == 4: planar value (Ch pre-offset by bOff*32)
            Ch[((size_t)(gc0 >> 5) * NTOK + gr) * 32 + (gc0 & 31)] = __float2half(v0);
            Ch[((size_t)(gc1 >> 5) * NTOK + gr) * 32 + (gc1 & 31)] = __float2half(v1);
        }
    }
}

// ================= pre: warp-per-token + weight prep slice =================
__global__ void pre_kernel(const float* __restrict__ x,
                           const float* __restrict__ gamma,
                           const float* __restrict__ beta,
                           const float* __restrict__ pos,
                           const float* __restrict__ Wv, const float* __restrict__ Wo,
                           const float* __restrict__ Wa, const float* __restrict__ Wout,
                           const float* __restrict__ Wf1, const float* __restrict__ Wf2) {
    const int wid = threadIdx.x >> 5, lane = threadIdx.x & 31;
    const int t = blockIdx.x * 8 + wid;

    int gid = blockIdx.x * 256 + threadIdx.x;
    if (gid < 753664) {
        int i = gid;
        const float* W; __half* B; int K, N, rowOff, i2;
        if (i < 65536)        { W = Wv;  B = w_v;  K = 256;  N = 256;  rowOff = 0;   i2 = i; }
        else if (i < 131072)  { W = Wo;  B = w_qa; K = 256;  N = 256;  rowOff = 0;   i2 = i - 65536; }
        else if (i < 163840)  { W = Wa;  B = w_qa; K = 256;  N = 128;  rowOff = 256; i2 = i - 131072; }
        else if (i < 229376)  { W = Wout;B = w_o;  K = 256;  N = 256;  rowOff = 0;   i2 = i - 163840; }
        else if (i < 491520)  { W = Wf1; B = w_f1; K = 256;  N = 1024; rowOff = 0;   i2 = i - 229376; }
        else                  { W = Wf2; B = w_f2; K = 1024; N = 256;  rowOff = 0;   i2 = i - 491520; }
        int k = i2 / N, n = i2 - k * N;
        B[(size_t)(n + rowOff) * K + k] = __float2half(W[i2]);
    }

    const float4* rowX = (const float4*)(x + (size_t)t * 256);
    float4 va = rowX[lane], vb = rowX[lane + 32];

    {
        uint2 o0, o1;
        __half2 p0 = __floats2half2_rn(va.x, va.y), p1 = __floats2half2_rn(va.z, va.w);
        __half2 p2 = __floats2half2_rn(vb.x, vb.y), p3 = __floats2half2_rn(vb.z, vb.w);
        o0.x = *(uint32_t*)&p0; o0.y = *(uint32_t*)&p1;
        o1.x = *(uint32_t*)&p2; o1.y = *(uint32_t*)&p3;
        ((uint2*)g_srcH)[(size_t)t * 64 + lane] = o0;
        ((uint2*)g_srcH)[(size_t)t * 64 + 32 + lane] = o1;
    }

    float s  = va.x + va.y + va.z + va.w + vb.x + vb.y + vb.z + vb.w;
    float s2 = va.x*va.x + va.y*va.y + va.z*va.z + va.w*va.w
             + vb.x*vb.x + vb.y*vb.y + vb.z*vb.z + vb.w*vb.w;
    #pragma unroll
    for (int o = 16; o; o >>= 1) {
        s  += __shfl_xor_sync(0xffffffffu, s,  o);
        s2 += __shfl_xor_sync(0xffffffffu, s2, o);
    }
    float mu  = s * (1.0f / D_MODEL);
    float var = s2 * (1.0f / D_MODEL) - mu * mu;
    float rr  = rsqrtf(var + 1e-5f);

    const float4* rowP = (const float4*)(pos + (size_t)t * 256);
    const float4* gmA = (const float4*)gamma;
    const float4* btA = (const float4*)beta;
    #pragma unroll
    for (int hfl = 0; hfl < 2; hfl++) {
        int idx = lane + hfl * 32;
        float4 v = hfl ? vb : va;
        float4 p = rowP[idx];
        float4 gm = gmA[idx], bt = btA[idx];
        float y0 = (v.x - mu) * rr * gm.x + bt.x + p.x;
        float y1 = (v.y - mu) * rr * gm.y + bt.y + p.y;
        float y2 = (v.z - mu) * rr * gm.z + bt.z + p.z;
        float y3 = (v.w - mu) * rr * gm.w + bt.w + p.w;
        uint2 o;
        __half2 q0 = __floats2half2_rn(y0, y1), q1 = __floats2half2_rn(y2, y3);
        o.x = *(uint32_t*)&q0; o.y = *(uint32_t*)&q1;
        ((uint2*)g_qH)[(size_t)t * 64 + idx] = o;
    }
}

// ================= ln2: warp-per-token, batch slice =================
__global__ void ln2_kernel(const float* __restrict__ x,
                           const float* __restrict__ gamma,
                           const float* __restrict__ beta,
                           int tokOff) {
    const int wid = threadIdx.x >> 5, lane = threadIdx.x & 31;
    const int t = tokOff + blockIdx.x * 8 + wid;

    const float4* rowX = (const float4*)(x + (size_t)t * 256);
    float4 va = rowX[lane], vb = rowX[lane + 32];

    float s  = va.x + va.y + va.z + va.w + vb.x + vb.y + vb.z + vb.w;
    float s2 = va.x*va.x + va.y*va.y + va.z*va.z + va.w*va.w
             + vb.x*vb.x + vb.y*vb.y + vb.z*vb.z + vb.w*vb.w;
    #pragma unroll
    for (int o = 16; o; o >>= 1) {
        s  += __shfl_xor_sync(0xffffffffu, s,  o);
        s2 += __shfl_xor_sync(0xffffffffu, s2, o);
    }
    float mu  = s * (1.0f / D_MODEL);
    float var = s2 * (1.0f / D_MODEL) - mu * mu;
    float rr  = rsqrtf(var + 1e-5f);

    const float4* gmA = (const float4*)gamma;
    const float4* btA = (const float4*)beta;
    #pragma unroll
    for (int hfl = 0; hfl < 2; hfl++) {
        int idx = lane + hfl * 32;
        float4 v = hfl ? vb : va;
        float4 gm = gmA[idx], bt = btA[idx];
        float y0 = (v.x - mu) * rr * gm.x + bt.x;
        float y1 = (v.y - mu) * rr * gm.y + bt.y;
        float y2 = (v.z - mu) * rr * gm.z + bt.z;
        float y3 = (v.w - mu) * rr * gm.w + bt.w;
        uint2 o;
        __half2 q0 = __floats2half2_rn(y0, y1), q1 = __floats2half2_rn(y2, y3);
        o.x = *(uint32_t*)&q0; o.y = *(uint32_t*)&q1;
        ((uint2*)g_h2H)[(size_t)t * 64 + idx] = o;
    }
}

// ================= deform (R13): fp16 bilinear blend, batch slice =================
__global__ void deform_kernel(const float* __restrict__ ref, int bIdx) {
    const int lvH[4] = {128, 64, 32, 16};
    const int lvW[4] = {128, 64, 32, 16};
    const int lvS[4] = {0, 16384, 20480, 21504};

    int g = blockIdx.x * 8 + (threadIdx.x >> 5);    // 0 .. SLEN*NHEADS-1
    int lane = threadIdx.x & 31;
    int qi = g / NHEADS;
    int h  = g - qi * NHEADS;
    int tok = bIdx * SLEN + qi;

    float offv = g_off[(size_t)tok * 256 + h * 32 + lane];
    float refv = (lane < 8) ? ref[(size_t)tok * 8 + lane] : 0.f;
    float lg   = (lane < 16) ? g_attn[(size_t)tok * 128 + h * 16 + lane] : -1e30f;

    float mx = lg;
    #pragma unroll
    for (int o = 8; o; o >>= 1) mx = fmaxf(mx, __shfl_xor_sync(0xffffffffu, mx, o));
    float e = (lane < 16) ? __expf(lg - mx) : 0.f;
    float se = e;
    #pragma unroll
    for (int o = 8; o; o >>= 1) se += __shfl_xor_sync(0xffffffffu, se, o);
    float wnorm = e / se;

    uint32_t c00, c01, c10, c11;
    uint32_t uh00, uh01, uh10, uh11;
    float wat;
    {
        const int sidx = lane & 15;
        const int lvl  = sidx >> 2;
        const int Ww = lvW[lvl], Hh = lvH[lvl];
        float rx = __shfl_sync(0xffffffffu, refv, lvl * 2 + 0);
        float ry = __shfl_sync(0xffffffffu, refv, lvl * 2 + 1);
        float ox = __shfl_sync(0xffffffffu, offv, sidx * 2 + 0);
        float oy = __shfl_sync(0xffffffffu, offv, sidx * 2 + 1);
        wat = __shfl_sync(0xffffffffu, wnorm, sidx);

        float x = fmaf(rx, (float)Ww, ox) - 0.5f;
        float y = fmaf(ry, (float)Hh, oy) - 0.5f;
        float x0f = floorf(x), y0f = floorf(y);
        int x0 = (int)x0f, y0 = (int)y0f;
        float wx = x - x0f, wy = y - y0f;
        int x1 = x0 + 1, y1 = y0 + 1;

        float vx0 = ((unsigned)x0 < (unsigned)Ww) ? 1.f : 0.f;
        float vx1 = ((unsigned)x1 < (unsigned)Ww) ? 1.f : 0.f;
        float vy0 = ((unsigned)y0 < (unsigned)Hh) ? 1.f : 0.f;
        float vy1 = ((unsigned)y1 < (unsigned)Hh) ? 1.f : 0.f;

        int x0c = min(max(x0, 0), Ww - 1), x1c = min(max(x1, 0), Ww - 1);
        int y0c = min(max(y0, 0), Hh - 1), y1c = min(max(y1, 0), Hh - 1);

        uint32_t pb = (uint32_t)h * NTOK + (uint32_t)(bIdx * SLEN + lvS[lvl]);
        uint32_t r0 = pb + (uint32_t)(y0c * Ww), r1 = pb + (uint32_t)(y1c * Ww);
        c00 = (r0 + (uint32_t)x0c) * 8u; c01 = (r0 + (uint32_t)x1c) * 8u;
        c10 = (r1 + (uint32_t)x0c) * 8u; c11 = (r1 + (uint32_t)x1c) * 8u;

        float wx0 = 1.f - wx, wy0 = 1.f - wy;
        __half2 t0 = __float2half2_rn(wx0 * wy0 * (vx0 * vy0));
        __half2 t1 = __float2half2_rn(wx  * wy0 * (vx1 * vy0));
        __half2 t2 = __float2half2_rn(wx0 * wy  * (vx0 * vy1));
        __half2 t3 = __float2half2_rn(wx  * wy  * (vx1 * vy1));
        uh00 = *(uint32_t*)&t0; uh01 = *(uint32_t*)&t1;
        uh10 = *(uint32_t*)&t2; uh11 = *(uint32_t*)&t3;
    }

    const int q = lane >> 3;
    const uint32_t li = (uint32_t)(lane & 7);
    const uint2* vbase = (const uint2*)g_valueH;
    float4 acc = make_float4(0.f, 0.f, 0.f, 0.f);
    #pragma unroll
    for (int it = 0; it < 4; it++) {
        const int sp = it * 4 + q;
        uint32_t a00 = __shfl_sync(0xffffffffu, c00, sp) + li;
        uint32_t a01 = __shfl_sync(0xffffffffu, c01, sp) + li;
        uint32_t a10 = __shfl_sync(0xffffffffu, c10, sp) + li;
        uint32_t a11 = __shfl_sync(0xffffffffu, c11, sp) + li;
        uint32_t b00 = __shfl_sync(0xffffffffu, uh00, sp);
        uint32_t b01 = __shfl_sync(0xffffffffu, uh01, sp);
        uint32_t b10 = __shfl_sync(0xffffffffu, uh10, sp);
        uint32_t b11 = __shfl_sync(0xffffffffu, uh11, sp);
        float w = __shfl_sync(0xffffffffu, wat, sp);
        uint2 r00 = vbase[a00];
        uint2 r01 = vbase[a01];
        uint2 r10 = vbase[a10];
        uint2 r11 = vbase[a11];
        __half2 blo = __hmul2(*(__half2*)&b00, *(__half2*)&r00.x);
        blo = __hfma2(*(__half2*)&b01, *(__half2*)&r01.x, blo);
        blo = __hfma2(*(__half2*)&b10, *(__half2*)&r10.x, blo);
        blo = __hfma2(*(__half2*)&b11, *(__half2*)&r11.x, blo);
        __half2 bhi = __hmul2(*(__half2*)&b00, *(__half2*)&r00.y);
        bhi = __hfma2(*(__half2*)&b01, *(__half2*)&r01.y, bhi);
        bhi = __hfma2(*(__half2*)&b10, *(__half2*)&r10.y, bhi);
        bhi = __hfma2(*(__half2*)&b11, *(__half2*)&r11.y, bhi);
        float2 f0 = __half22float2(blo);
        float2 f1 = __half22float2(bhi);
        acc.x = fmaf(f0.x, w, acc.x);
        acc.y = fmaf(f0.y, w, acc.y);
        acc.z = fmaf(f1.x, w, acc.z);
        acc.w = fmaf(f1.y, w, acc.w);
    }
    #pragma unroll
    for (int o = 8; o <= 16; o <<= 1) {
        acc.x += __shfl_xor_sync(0xffffffffu, acc.x, o);
        acc.y += __shfl_xor_sync(0xffffffffu, acc.y, o);
        acc.z += __shfl_xor_sync(0xffffffffu, acc.z, o);
        acc.w += __shfl_xor_sync(0xffffffffu, acc.w, o);
    }
    if (lane < 8) {
        uint2 outv;
        __half2 h0 = __floats2half2_rn(acc.x, acc.y);
        __half2 h1 = __floats2half2_rn(acc.z, acc.w);
        outv.x = *(const uint32_t*)&h0;
        outv.y = *(const uint32_t*)&h1;
        ((uint2*)g_sampH)[(uint32_t)tok * 64u + (uint32_t)h * 8u + li] = outv;
    }
}

// ================= launch: batch-split dual-stream pipeline =================
extern "C" void kernel_launch(void* const* d_in, const int* in_sizes, int n_in,
                              void* d_out, int out_size) {
    const float* src  = (const float*)d_in[0];
    const float* pos  = (const float*)d_in[1];
    const float* refp = (const float*)d_in[2];
    const float* n1g = (const float*)d_in[5];
    const float* n1b = (const float*)d_in[6];
    const float* n2g = (const float*)d_in[7];
    const float* n2b = (const float*)d_in[8];
    const float* Wv  = (const float*)d_in[9];
    const float* bv  = (const float*)d_in[10];
    const float* Wo  = (const float*)d_in[11];
    const float* bo  = (const float*)d_in[12];
    const float* Wa  = (const float*)d_in[13];
    const float* ba  = (const float*)d_in[14];
    const float* Wout= (const float*)d_in[15];
    const float* bout= (const float*)d_in[16];
    const float* Wf1 = (const float*)d_in[17];
    const float* bf1 = (const float*)d_in[18];
    const float* Wf2 = (const float*)d_in[19];
    const float* bf2 = (const float*)d_in[20];
    float* out = (float*)d_out;

    __half *srcH, *qH, *sampH, *h2H, *ffnH, *valH;
    __half *wv, *wqa, *wo, *wf1, *wf2;
    float *pOff, *pAttn, *pSrc2;
    cudaGetSymbolAddress((void**)&srcH, g_srcH);
    cudaGetSymbolAddress((void**)&qH,   g_qH);
    cudaGetSymbolAddress((void**)&sampH,g_sampH);
    cudaGetSymbolAddress((void**)&h2H,  g_h2H);
    cudaGetSymbolAddress((void**)&ffnH, g_ffnH);
    cudaGetSymbolAddress((void**)&valH, g_valueH);
    cudaGetSymbolAddress((void**)&wv,   w_v);
    cudaGetSymbolAddress((void**)&wqa,  w_qa);
    cudaGetSymbolAddress((void**)&wo,   w_o);
    cudaGetSymbolAddress((void**)&wf1,  w_f1);
    cudaGetSymbolAddress((void**)&wf2,  w_f2);
    cudaGetSymbolAddress((void**)&pOff,  g_off);
    cudaGetSymbolAddress((void**)&pAttn, g_attn);
    cudaGetSymbolAddress((void**)&pSrc2, g_src2);

    cudaFuncSetAttribute(mma_gemm<1>, cudaFuncAttributeMaxDynamicSharedMemorySize, GEMM_SMEM);
    cudaFuncSetAttribute(mma_gemm<2>, cudaFuncAttributeMaxDynamicSharedMemorySize, GEMM_SMEM);
    cudaFuncSetAttribute(mma_gemm<3>, cudaFuncAttributeMaxDynamicSharedMemorySize, GEMM_SMEM);
    cudaFuncSetAttribute(mma_gemm<4>, cudaFuncAttributeMaxDynamicSharedMemorySize, GEMM_SMEM);

    static cudaStream_t sB = nullptr;
    static cudaEvent_t evPre = nullptr, evB = nullptr;
    if (!sB) {
        cudaStreamCreateWithFlags(&sB, cudaStreamNonBlocking);
        cudaEventCreateWithFlags(&evPre, cudaEventDisableTiming);
        cudaEventCreateWithFlags(&evB,   cudaEventDisableTiming);
    }

    dim3 t256(256), t128(128);
    const int MBb = SLEN / 128;   // 170 row-tiles per batch

    // stage 0: shared prep (weights + src/q fp16) on main stream
    pre_kernel<<<NTOK / 8, t256>>>(src, n1g, n1b, pos, Wv, Wo, Wa, Wout, Wf1, Wf2);
    cudaEventRecord(evPre, 0);
    cudaStreamWaitEvent(sB, evPre, 0);

    // per-batch pipelines: batch 0 on stream 0, batch 1 on sB
    for (int b = 0; b < 2; b++) {
        cudaStream_t st = (b == 0) ? (cudaStream_t)0 : sB;
        const size_t to = (size_t)b * SLEN;            // token offset
        const __half* srcHb = srcH + to * 256;
        const __half* qHb   = qH   + to * 256;
        __half*  valHb  = valH + to * 32;              // planar batch offset (see EPI4)
        float*   offb   = pOff  + to * 256;
        float*   attnb  = pAttn + to * 128;
        __half*  sampb  = sampH + to * 256;
        float*   src2b  = pSrc2 + to * 256;
        const float* srcb = src + to * 256;
        __half*  h2b    = h2H  + to * 256;
        __half*  ffnb   = ffnH + to * 1024;
        float*   outb   = out  + to * 256;

        mma_gemm<4><<<dim3(2, MBb), t128, GEMM_SMEM, st>>>(srcHb, wv, bv, nullptr,
                                                           nullptr, nullptr, valHb, 256, 256);
        mma_gemm<3><<<dim3(3, MBb), t128, GEMM_SMEM, st>>>(qHb, wqa, bo, ba,
                                                           offb, attnb, nullptr, 384, 256);
        deform_kernel<<<(SLEN * NHEADS) / 8, t256, 0, st>>>(refp, b);
        mma_gemm<2><<<dim3(2, MBb), t128, GEMM_SMEM, st>>>(sampb, wo, bout, srcb,
                                                           src2b, nullptr, nullptr, 256, 256);
        ln2_kernel<<<SLEN / 8, t256, 0, st>>>(pSrc2, n2g, n2b, (int)to);
        mma_gemm<1><<<dim3(8, MBb), t128, GEMM_SMEM, st>>>(h2b, wf1, bf1, nullptr,
                                                           nullptr, nullptr, ffnb, 1024, 256);
        mma_gemm<2><<<dim3(2, MBb), t128, GEMM_SMEM, st>>>(ffnb, wf2, bf2, src2b,
                                                           outb, nullptr, nullptr, 256, 1024);
    }

    // join sB back into the main stream
    cudaEventRecord(evB, sB);
    cudaStreamWaitEvent(0, evB, 0);
}